// round 2
// baseline (speedup 1.0000x reference)
#include <cuda_runtime.h>
#include <math.h>

// ---------------- scratch ----------------
__device__ float g_flow0 [8*256*3];
__device__ float g_flow0us[8*512*3];
__device__ float g_in1   [8*256];
__device__ float g_in2   [8*256];
__device__ int   g_fps1  [8*512];
__device__ int   g_fps2  [8*1024];
__device__ float g_x0a   [8*512*16*6];
__device__ float g_ya    [8*8192*32];
__device__ float g_yb    [8*8192*32];
__device__ float g_yc    [8*8192*64];
__device__ float g_cf2   [8*512*64];
__device__ float g_cf1   [8*1024*64];
__device__ float g_x0b   [(size_t)8*1024*16*67];
__device__ float g_za    [(size_t)8*16384*64];
__device__ float g_zb    [(size_t)8*16384*64];
__device__ float g_zc    [(size_t)8*16384*128];
__device__ float g_cf1o  [8*1024*128];
__device__ float g_part  [(size_t)8*512*128*2];
__device__ float g_ab    [8*128*2];

// ---------------- FPS --------------------------------------------------------
// blocks 0..7: batch b over pc1_l2 (N=512) -> fps1; 8..15: pc1_l1 (N=1024) -> fps2
__global__ __launch_bounds__(256) void k_fps(const float* __restrict__ pcA,
                                             const float* __restrict__ pcB,
                                             int* __restrict__ o1, int* __restrict__ o2)
{
    __shared__ float sx[1024], sy[1024], sz[1024];
    __shared__ float rv[8]; __shared__ int ri[8]; __shared__ int sfar;
    int blk = blockIdx.x; int b, N; const float* src; int* out;
    if (blk < 8) { b = blk;   N = 512;  src = pcA; out = o1 + b*512; }
    else         { b = blk-8; N = 1024; src = pcB; out = o2 + b*1024; }
    int t = threadIdx.x;
    float px[4], py[4], pz[4], md[4];
    int NP = N >> 8;
    for (int j = 0; j < NP; j++) {
        int p = t + j*256;
        px[j] = src[(b*3+0)*N + p];
        py[j] = src[(b*3+1)*N + p];
        pz[j] = src[(b*3+2)*N + p];
        sx[p] = px[j]; sy[p] = py[j]; sz[p] = pz[j];
        md[j] = 1e10f;
    }
    __syncthreads();
    int far = 0;
    for (int it = 0; it < N; it++) {
        if (t == 0) out[it] = far;
        float fx = sx[far], fy = sy[far], fz = sz[far];
        float bv = -1.f; int bi = 0x7fffffff;
        for (int j = 0; j < NP; j++) {
            float dx = px[j]-fx, dy = py[j]-fy, dz = pz[j]-fz;
            float d = dx*dx + dy*dy + dz*dz;
            md[j] = fminf(md[j], d);
            if (md[j] > bv) { bv = md[j]; bi = t + j*256; }
        }
        #pragma unroll
        for (int o = 16; o; o >>= 1) {
            float ov = __shfl_down_sync(0xffffffffu, bv, o);
            int   oi = __shfl_down_sync(0xffffffffu, bi, o);
            if (ov > bv || (ov == bv && oi < bi)) { bv = ov; bi = oi; }
        }
        int w = t >> 5;
        if ((t & 31) == 0) { rv[w] = bv; ri[w] = bi; }
        __syncthreads();
        if (t < 32) {
            float v2 = (t < 8) ? rv[t] : -2.f;
            int   i2 = (t < 8) ? ri[t] : 0x7fffffff;
            #pragma unroll
            for (int o = 4; o; o >>= 1) {
                float ov = __shfl_down_sync(0xffffffffu, v2, o);
                int   oi = __shfl_down_sync(0xffffffffu, i2, o);
                if (ov > v2 || (ov == v2 && oi < i2)) { v2 = ov; i2 = oi; }
            }
            if (t == 0) sfar = i2;
        }
        __syncthreads();
        far = sfar;
    }
}

// ---------------- feature inverse norms --------------------------------------
__global__ void k_inorm(const float* __restrict__ f1, const float* __restrict__ f2,
                        float* __restrict__ o1, float* __restrict__ o2)
{
    int b = blockIdx.x, which = blockIdx.y, n = threadIdx.x;
    const float* f = which ? f2 : f1;
    float* o = which ? o2 : o1;
    float s = 0.f;
    for (int c = 0; c < 256; c++) { float v = f[(b*256+c)*256 + n]; s += v*v; }
    o[b*256+n] = 1.0f / sqrtf(s + 1e-8f);
}

// ---------------- global correlation -> flow0 --------------------------------
__global__ __launch_bounds__(256) void k_corr(const float* __restrict__ f1,
                                              const float* __restrict__ f2,
                                              const float* __restrict__ in1,
                                              const float* __restrict__ in2,
                                              const float* __restrict__ p1g,
                                              const float* __restrict__ p2g,
                                              const float* __restrict__ epsin,
                                              float* __restrict__ flow0)
{
    __shared__ float sA[32*64], sB[32*256];
    __shared__ float si1[64], si2[256], sq1[64], sq2[256];
    __shared__ float sp1[64*3], sp2[256*3];
    const int b = blockIdx.y, n0 = blockIdx.x*64, tid = threadIdx.x;
    for (int i = tid; i < 64; i += 256) {
        si1[i] = in1[b*256 + n0 + i];
        float X = p1g[(b*3+0)*256+n0+i], Y = p1g[(b*3+1)*256+n0+i], Z = p1g[(b*3+2)*256+n0+i];
        sp1[i*3] = X; sp1[i*3+1] = Y; sp1[i*3+2] = Z; sq1[i] = X*X+Y*Y+Z*Z;
    }
    for (int i = tid; i < 256; i += 256) {
        si2[i] = in2[b*256+i];
        float X = p2g[(b*3+0)*256+i], Y = p2g[(b*3+1)*256+i], Z = p2g[(b*3+2)*256+i];
        sp2[i*3] = X; sp2[i*3+1] = Y; sp2[i*3+2] = Z; sq2[i] = X*X+Y*Y+Z*Z;
    }
    const float inv_eps = 1.0f / (expf(epsin[0]) + 0.03f);
    const int ty = tid >> 5, tx = tid & 31;
    float acc[8][8];
    #pragma unroll
    for (int i = 0; i < 8; i++)
        #pragma unroll
        for (int j = 0; j < 8; j++) acc[i][j] = 0.f;
    for (int cc = 0; cc < 256; cc += 32) {
        __syncthreads();
        for (int i = tid; i < 2048; i += 256) {
            int c = i >> 6, n = i & 63;
            sA[i] = f1[(b*256 + cc + c)*256 + n0 + n];
        }
        for (int i = tid; i < 8192; i += 256) {
            int c = i >> 8, m = i & 255;
            sB[i] = f2[(b*256 + cc + c)*256 + m];
        }
        __syncthreads();
        #pragma unroll 4
        for (int c = 0; c < 32; c++) {
            float a[8], bv[8];
            #pragma unroll
            for (int i = 0; i < 8; i++) a[i] = sA[c*64 + ty*8 + i];
            #pragma unroll
            for (int j = 0; j < 8; j++) bv[j] = sB[c*256 + tx + 32*j];
            #pragma unroll
            for (int i = 0; i < 8; i++)
                #pragma unroll
                for (int j = 0; j < 8; j++) acc[i][j] = fmaf(a[i], bv[j], acc[i][j]);
        }
    }
    #pragma unroll
    for (int i = 0; i < 8; i++) {
        int n = ty*8 + i;
        float i1v = si1[n], q1 = sq1[n];
        float px = sp1[n*3], py = sp1[n*3+1], pz = sp1[n*3+2];
        float s0 = 0.f, s1 = 0.f, s2 = 0.f, s3 = 0.f;
        #pragma unroll
        for (int j = 0; j < 8; j++) {
            int m = tx + 32*j;
            float Cv = 1.0f - acc[i][j]*i1v*si2[m];
            float qx = sp2[m*3], qy = sp2[m*3+1], qz = sp2[m*3+2];
            float dm = q1 + sq2[m] - 2.0f*(px*qx + py*qy + pz*qz);
            float cv = (dm < 100.0f) ? expf(-Cv*inv_eps) : 0.0f;
            s0 += cv; s1 += cv*qx; s2 += cv*qy; s3 += cv*qz;
        }
        #pragma unroll
        for (int o = 16; o; o >>= 1) {
            s0 += __shfl_down_sync(0xffffffffu, s0, o);
            s1 += __shfl_down_sync(0xffffffffu, s1, o);
            s2 += __shfl_down_sync(0xffffffffu, s2, o);
            s3 += __shfl_down_sync(0xffffffffu, s3, o);
        }
        if (tx == 0) {
            float inv = 1.0f / (s0 + 1e-8f);
            int gn = n0 + n;
            flow0[(b*256+gn)*3+0] = s1*inv - px;
            flow0[(b*256+gn)*3+1] = s2*inv - py;
            flow0[(b*256+gn)*3+2] = s3*inv - pz;
        }
    }
}

// ---------------- feature propagation (3-NN inverse-distance) ----------------
template <int NS, int CH, bool TOUT>
__global__ __launch_bounds__(128) void k_prop(const float* __restrict__ x1,
                                              const float* __restrict__ x2,
                                              const float* __restrict__ f,
                                              float* __restrict__ o, int ND)
{
    __shared__ float4 sp[NS];
    const int b = blockIdx.y, t = threadIdx.x;
    for (int i = t; i < NS; i += 128) {
        float X = x2[(b*3+0)*NS+i], Y = x2[(b*3+1)*NS+i], Z = x2[(b*3+2)*NS+i];
        sp[i] = make_float4(X, Y, Z, X*X+Y*Y+Z*Z);
    }
    __syncthreads();
    int n = blockIdx.x*128 + t;
    float x = x1[(b*3+0)*ND+n], y = x1[(b*3+1)*ND+n], z = x1[(b*3+2)*ND+n];
    float q = x*x + y*y + z*z;
    float d0 = 1e30f, d1 = 1e30f, d2 = 1e30f;
    int i0 = 0, i1 = 0, i2 = 0;
    for (int m = 0; m < NS; m++) {
        float4 P = sp[m];
        float d = q + P.w - 2.0f*(x*P.x + y*P.y + z*P.z);
        if (d < d2) {
            if (d < d1) {
                if (d < d0) { d2=d1;i2=i1; d1=d0;i1=i0; d0=d;i0=m; }
                else        { d2=d1;i2=i1; d1=d;i1=m; }
            } else          { d2=d;i2=m; }
        }
    }
    float w0 = 1.0f/(d0+1e-8f), w1 = 1.0f/(d1+1e-8f), w2 = 1.0f/(d2+1e-8f);
    float ws = 1.0f/(w0+w1+w2); w0 *= ws; w1 *= ws; w2 *= ws;
    const float* fa = &f[((size_t)b*NS+i0)*CH];
    const float* fb = &f[((size_t)b*NS+i1)*CH];
    const float* fc = &f[((size_t)b*NS+i2)*CH];
    if (CH % 4 == 0) {
        for (int c = 0; c < CH; c += 4) {
            float4 A = *(const float4*)&fa[c];
            float4 Bq = *(const float4*)&fb[c];
            float4 Cq = *(const float4*)&fc[c];
            float o0 = w0*A.x + w1*Bq.x + w2*Cq.x;
            float o1 = w0*A.y + w1*Bq.y + w2*Cq.y;
            float o2 = w0*A.z + w1*Bq.z + w2*Cq.z;
            float o3 = w0*A.w + w1*Bq.w + w2*Cq.w;
            if (TOUT) {
                o[((size_t)b*CH+c+0)*ND+n] = o0;
                o[((size_t)b*CH+c+1)*ND+n] = o1;
                o[((size_t)b*CH+c+2)*ND+n] = o2;
                o[((size_t)b*CH+c+3)*ND+n] = o3;
            } else {
                *(float4*)&o[((size_t)b*ND+n)*CH+c] = make_float4(o0,o1,o2,o3);
            }
        }
    } else {
        for (int c = 0; c < CH; c++) {
            float ov = w0*fa[c] + w1*fb[c] + w2*fc[c];
            if (TOUT) o[((size_t)b*CH+c)*ND+n] = ov;
            else      o[((size_t)b*ND+n)*CH+c] = ov;
        }
    }
}

// ---------------- SA1 grouping: kNN-16 + gather (features staged in smem) ----
__global__ __launch_bounds__(128) void k_g1(const float* __restrict__ xyz,
                                            const float* __restrict__ fl,
                                            const int* __restrict__ fps,
                                            float* __restrict__ x0)
{
    __shared__ float4 sp[512];
    __shared__ float sf[512*3];
    const int b = blockIdx.y, t = threadIdx.x;
    for (int i = t; i < 512; i += 128) {
        float X = xyz[(b*3+0)*512+i], Y = xyz[(b*3+1)*512+i], Z = xyz[(b*3+2)*512+i];
        sp[i] = make_float4(X, Y, Z, X*X+Y*Y+Z*Z);
        sf[i*3+0] = fl[((size_t)b*512+i)*3+0];
        sf[i*3+1] = fl[((size_t)b*512+i)*3+1];
        sf[i*3+2] = fl[((size_t)b*512+i)*3+2];
    }
    __syncthreads();
    int s = blockIdx.x*128 + t;
    int c = fps[b*512 + s];
    float4 cp = sp[c];
    float nd[16]; int ni[16];
    #pragma unroll
    for (int k = 0; k < 16; k++) { nd[k] = 1e30f; ni[k] = 0; }
    for (int m = 0; m < 512; m++) {
        float4 P = sp[m];
        float d = cp.w + P.w - 2.0f*(cp.x*P.x + cp.y*P.y + cp.z*P.z);
        if (d < nd[15]) {
            float cd = d; int ci = m;
            #pragma unroll
            for (int k = 0; k < 16; k++)
                if (cd < nd[k]) { float td=nd[k]; int ti=ni[k]; nd[k]=cd; ni[k]=ci; cd=td; ci=ti; }
        }
    }
    float* o = &x0[((size_t)(b*512+s)*16)*6];
    #pragma unroll
    for (int k = 0; k < 16; k++) {
        float4 P = sp[ni[k]];
        o[k*6+0] = P.x - cp.x; o[k*6+1] = P.y - cp.y; o[k*6+2] = P.z - cp.z;
        o[k*6+3] = sf[ni[k]*3+0]; o[k*6+4] = sf[ni[k]*3+1]; o[k*6+5] = sf[ni[k]*3+2];
    }
}

// ---------------- SA2 grouping (features gathered from gmem) -----------------
__global__ __launch_bounds__(256) void k_g2(const float* __restrict__ xyz,
                                            const float* __restrict__ feat,
                                            const int* __restrict__ fps,
                                            float* __restrict__ x0)
{
    __shared__ float4 sp[1024];
    const int b = blockIdx.y, t = threadIdx.x;
    for (int i = t; i < 1024; i += 256) {
        float X = xyz[(b*3+0)*1024+i], Y = xyz[(b*3+1)*1024+i], Z = xyz[(b*3+2)*1024+i];
        sp[i] = make_float4(X, Y, Z, X*X+Y*Y+Z*Z);
    }
    __syncthreads();
    int s = blockIdx.x*256 + t;
    int c = fps[b*1024 + s];
    float4 cp = sp[c];
    float nd[16]; int ni[16];
    #pragma unroll
    for (int k = 0; k < 16; k++) { nd[k] = 1e30f; ni[k] = 0; }
    for (int m = 0; m < 1024; m++) {
        float4 P = sp[m];
        float d = cp.w + P.w - 2.0f*(cp.x*P.x + cp.y*P.y + cp.z*P.z);
        if (d < nd[15]) {
            float cd = d; int ci = m;
            #pragma unroll
            for (int k = 0; k < 16; k++)
                if (cd < nd[k]) { float td=nd[k]; int ti=ni[k]; nd[k]=cd; ni[k]=ci; cd=td; ci=ti; }
        }
    }
    float* o = &x0[((size_t)(b*1024+s)*16)*67];
    for (int k = 0; k < 16; k++) {
        float4 P = sp[ni[k]];
        o[k*67+0] = P.x - cp.x; o[k*67+1] = P.y - cp.y; o[k*67+2] = P.z - cp.z;
        const float4* fp = (const float4*)&feat[((size_t)b*1024 + ni[k])*64];
        #pragma unroll
        for (int j = 0; j < 16; j++) {
            float4 v = fp[j];
            o[k*67+3+j*4+0] = v.x; o[k*67+3+j*4+1] = v.y;
            o[k*67+3+j*4+2] = v.z; o[k*67+3+j*4+3] = v.w;
        }
    }
}

// ---------------- 1x1 conv (+ prev-layer IN+relu on load) + partial stats ----
template <int CIN, int COUT, int ACT>
__global__ __launch_bounds__(128) void k_conv(const float* __restrict__ x,
                                              const float* __restrict__ w,
                                              const float* __restrict__ ab,
                                              float* __restrict__ y,
                                              float* __restrict__ part,
                                              int M, int nblk)
{
    constexpr int NCG = COUT/16, RG = 128/NCG, RPT = (CIN >= 64) ? 2 : 4;
    constexpr int TR = RG*RPT, PAD = CIN + 1;
    __shared__ __align__(16) float sw[CIN*COUT];
    __shared__ float sx[TR*PAD], ss1[COUT], ss2[COUT], sa[CIN], sbb[CIN];
    const int t = threadIdx.x, blk = blockIdx.x, b = blockIdx.y;
    for (int i = t; i < CIN*COUT; i += 128) sw[i] = w[i];
    if (ACT)
        for (int i = t; i < CIN; i += 128) {
            sa[i]  = ab[(b*CIN+i)*2];
            sbb[i] = ab[(b*CIN+i)*2+1];
        }
    if (t < COUT) { ss1[t] = 0.f; ss2[t] = 0.f; }
    if (ACT) __syncthreads();
    const float* xs = x + ((size_t)b*M + (size_t)blk*TR)*CIN;
    for (int i = t; i < TR*CIN; i += 128) {
        int r = i / CIN, c = i - r*CIN;
        float v = xs[i];
        if (ACT) { v = fmaf(v, sa[c], sbb[c]); v = fmaxf(v, 0.f); }
        sx[r*PAD + c] = v;
    }
    __syncthreads();
    const int rg = t / NCG, cg = t - rg*NCG;
    float acc[RPT][16];
    #pragma unroll
    for (int r = 0; r < RPT; r++)
        #pragma unroll
        for (int j = 0; j < 16; j++) acc[r][j] = 0.f;
    for (int k = 0; k < CIN; k++) {
        float xv[RPT];
        #pragma unroll
        for (int r = 0; r < RPT; r++) xv[r] = sx[(rg*RPT+r)*PAD + k];
        const float4* wp = (const float4*)&sw[k*COUT + cg*16];
        float4 w0 = wp[0], w1 = wp[1], w2 = wp[2], w3 = wp[3];
        float wv[16] = {w0.x,w0.y,w0.z,w0.w, w1.x,w1.y,w1.z,w1.w,
                        w2.x,w2.y,w2.z,w2.w, w3.x,w3.y,w3.z,w3.w};
        #pragma unroll
        for (int r = 0; r < RPT; r++)
            #pragma unroll
            for (int j = 0; j < 16; j++) acc[r][j] = fmaf(xv[r], wv[j], acc[r][j]);
    }
    float* yp = y + ((size_t)b*M + (size_t)blk*TR)*COUT;
    float s1[16], s2[16];
    #pragma unroll
    for (int j = 0; j < 16; j++) { s1[j] = 0.f; s2[j] = 0.f; }
    #pragma unroll
    for (int r = 0; r < RPT; r++) {
        int row = rg*RPT + r;
        #pragma unroll
        for (int j = 0; j < 16; j += 4)
            *(float4*)&yp[(size_t)row*COUT + cg*16 + j] =
                make_float4(acc[r][j], acc[r][j+1], acc[r][j+2], acc[r][j+3]);
        #pragma unroll
        for (int j = 0; j < 16; j++) { s1[j] += acc[r][j]; s2[j] += acc[r][j]*acc[r][j]; }
    }
    #pragma unroll
    for (int j = 0; j < 16; j++) {
        atomicAdd(&ss1[cg*16+j], s1[j]);
        atomicAdd(&ss2[cg*16+j], s2[j]);
    }
    __syncthreads();
    if (t < COUT) {
        part[(((size_t)b*nblk + blk)*COUT + t)*2 + 0] = ss1[t];
        part[(((size_t)b*nblk + blk)*COUT + t)*2 + 1] = ss2[t];
    }
}

// ---------------- IN stats finalize ------------------------------------------
template <int COUT>
__global__ void k_fin(const float* __restrict__ part, const float* __restrict__ gamma,
                      const float* __restrict__ beta, float* __restrict__ ab,
                      int nblk, float invn)
{
    int b = blockIdx.x, c = threadIdx.x;
    float s1 = 0.f, s2 = 0.f;
    for (int i = 0; i < nblk; i++) {
        s1 += part[(((size_t)b*nblk + i)*COUT + c)*2 + 0];
        s2 += part[(((size_t)b*nblk + i)*COUT + c)*2 + 1];
    }
    float mu = s1*invn;
    float var = s2*invn - mu*mu;
    float rs = 1.0f / sqrtf(var + 1e-5f);
    float A = gamma[c]*rs;
    ab[(b*COUT+c)*2 + 0] = A;
    ab[(b*COUT+c)*2 + 1] = beta[c] - mu*A;
}

// ---------------- norm+relu+maxpool over nsample ------------------------------
template <int COUT>
__global__ void k_pool(const float* __restrict__ y, const float* __restrict__ ab,
                       float* __restrict__ o)
{
    int s = blockIdx.x, b = blockIdx.y, c = threadIdx.x, S = gridDim.x;
    float A = ab[(b*COUT+c)*2], Bc = ab[(b*COUT+c)*2+1];
    const float* yp = y + ((size_t)(b*S + s)*16)*COUT + c;
    float m = 0.f;
    #pragma unroll
    for (int k = 0; k < 16; k++) {
        float v = fmaf(yp[(size_t)k*COUT], A, Bc);
        m = fmaxf(m, v);
    }
    o[((size_t)b*S + s)*COUT + c] = m;
}

// ---------------- launch -----------------------------------------------------
extern "C" void kernel_launch(void* const* d_in, const int* in_sizes, int n_in,
                              void* d_out, int out_size)
{
    const float* pc0 = (const float*)d_in[0];
    const float* pc1 = (const float*)d_in[1];
    const float* pc2 = (const float*)d_in[2];
    const float* pc3 = (const float*)d_in[3];
    const float* q3  = (const float*)d_in[4];
    const float* f1  = (const float*)d_in[5];
    const float* f2  = (const float*)d_in[6];
    const float* eps = (const float*)d_in[7];
    const float* w10 = (const float*)d_in[8];
    const float* w11 = (const float*)d_in[9];
    const float* w12 = (const float*)d_in[10];
    const float* g10 = (const float*)d_in[11]; const float* b10 = (const float*)d_in[12];
    const float* g11 = (const float*)d_in[13]; const float* b11 = (const float*)d_in[14];
    const float* g12 = (const float*)d_in[15]; const float* b12 = (const float*)d_in[16];
    const float* w20 = (const float*)d_in[17];
    const float* w21 = (const float*)d_in[18];
    const float* w22 = (const float*)d_in[19];
    const float* g20 = (const float*)d_in[20]; const float* b20 = (const float*)d_in[21];
    const float* g21 = (const float*)d_in[22]; const float* b21 = (const float*)d_in[23];
    const float* g22 = (const float*)d_in[24]; const float* b22 = (const float*)d_in[25];
    float* out = (float*)d_out;

    void *flow0, *flow0us, *in1, *in2, *fps1, *fps2, *x0a, *ya, *yb, *yc;
    void *cf2, *cf1, *x0b, *za, *zb, *zc, *cf1o, *part, *ab;
    cudaGetSymbolAddress(&flow0, g_flow0);
    cudaGetSymbolAddress(&flow0us, g_flow0us);
    cudaGetSymbolAddress(&in1, g_in1);
    cudaGetSymbolAddress(&in2, g_in2);
    cudaGetSymbolAddress(&fps1, g_fps1);
    cudaGetSymbolAddress(&fps2, g_fps2);
    cudaGetSymbolAddress(&x0a, g_x0a);
    cudaGetSymbolAddress(&ya, g_ya);
    cudaGetSymbolAddress(&yb, g_yb);
    cudaGetSymbolAddress(&yc, g_yc);
    cudaGetSymbolAddress(&cf2, g_cf2);
    cudaGetSymbolAddress(&cf1, g_cf1);
    cudaGetSymbolAddress(&x0b, g_x0b);
    cudaGetSymbolAddress(&za, g_za);
    cudaGetSymbolAddress(&zb, g_zb);
    cudaGetSymbolAddress(&zc, g_zc);
    cudaGetSymbolAddress(&cf1o, g_cf1o);
    cudaGetSymbolAddress(&part, g_part);
    cudaGetSymbolAddress(&ab, g_ab);

    k_fps<<<16, 256>>>(pc2, pc1, (int*)fps1, (int*)fps2);
    k_inorm<<<dim3(8,2), 256>>>(f1, f2, (float*)in1, (float*)in2);
    k_corr<<<dim3(4,8), 256>>>(f1, f2, (float*)in1, (float*)in2, pc3, q3, eps, (float*)flow0);
    k_prop<256,3,false><<<dim3(4,8), 128>>>(pc2, pc3, (float*)flow0, (float*)flow0us, 512);
    k_g1<<<dim3(4,8), 128>>>(pc2, (float*)flow0us, (int*)fps1, (float*)x0a);

    k_conv<6,32,0><<<dim3(32,8), 128>>>((float*)x0a, w10, (float*)ab, (float*)ya, (float*)part, 8192, 32);
    k_fin<32><<<8, 32>>>((float*)part, g10, b10, (float*)ab, 32, 1.0f/8192.0f);
    k_conv<32,32,1><<<dim3(32,8), 128>>>((float*)ya, w11, (float*)ab, (float*)yb, (float*)part, 8192, 32);
    k_fin<32><<<8, 32>>>((float*)part, g11, b11, (float*)ab, 32, 1.0f/8192.0f);
    k_conv<32,64,1><<<dim3(64,8), 128>>>((float*)yb, w12, (float*)ab, (float*)yc, (float*)part, 8192, 64);
    k_fin<64><<<8, 64>>>((float*)part, g12, b12, (float*)ab, 64, 1.0f/8192.0f);
    k_pool<64><<<dim3(512,8), 64>>>((float*)yc, (float*)ab, (float*)cf2);

    k_prop<512,64,false><<<dim3(8,8), 128>>>(pc1, pc2, (float*)cf2, (float*)cf1, 1024);
    k_g2<<<dim3(4,8), 256>>>(pc1, (float*)cf1, (int*)fps2, (float*)x0b);

    k_conv<67,64,0><<<dim3(256,8), 128>>>((float*)x0b, w20, (float*)ab, (float*)za, (float*)part, 16384, 256);
    k_fin<64><<<8, 64>>>((float*)part, g20, b20, (float*)ab, 256, 1.0f/16384.0f);
    k_conv<64,64,1><<<dim3(256,8), 128>>>((float*)za, w21, (float*)ab, (float*)zb, (float*)part, 16384, 256);
    k_fin<64><<<8, 64>>>((float*)part, g21, b21, (float*)ab, 256, 1.0f/16384.0f);
    k_conv<64,128,1><<<dim3(512,8), 128>>>((float*)zb, w22, (float*)ab, (float*)zc, (float*)part, 16384, 512);
    k_fin<128><<<8, 128>>>((float*)part, g22, b22, (float*)ab, 512, 1.0f/16384.0f);
    k_pool<128><<<dim3(1024,8), 128>>>((float*)zc, (float*)ab, (float*)cf1o);

    k_prop<1024,128,true><<<dim3(64,8), 128>>>(pc0, pc1, (float*)cf1o, out, 8192);
}

// round 4
// speedup vs baseline: 1.2272x; 1.2272x over previous
#include <cuda_runtime.h>
#include <math.h>

// ---------------- scratch ----------------
__device__ float g_flow0 [8*256*3];
__device__ float g_flow0us[8*512*3];
__device__ float g_in1   [8*256];
__device__ float g_in2   [8*256];
__device__ int   g_fps1  [8*512];
__device__ int   g_fps2  [8*1024];
__device__ float g_x0a   [8*512*16*8];
__device__ float g_ya    [8*8192*32];
__device__ float g_yb    [8*8192*32];
__device__ float g_yc    [8*8192*64];
__device__ float g_cf2   [8*512*64];
__device__ float g_cf1   [8*1024*64];
__device__ float g_x0b   [(size_t)8*1024*16*68];
__device__ float g_za    [(size_t)8*16384*64];
__device__ float g_zb    [(size_t)8*16384*64];
__device__ float g_zc    [(size_t)8*16384*128];
__device__ float g_cf1o  [8*1024*128];
__device__ float g_part  [(size_t)8*512*128*2];
__device__ float g_ab    [8*128*2];

// ---------------- FPS (REDUX-based, 1 barrier/iter) ---------------------------
template <int N, int NP>
__device__ __forceinline__ void fps_run(const float* __restrict__ src, int b,
                                        int* __restrict__ out,
                                        float4* sp, unsigned long long (*skey)[8])
{
    int t = threadIdx.x;
    float px[NP], py[NP], pz[NP], md[NP];
    #pragma unroll
    for (int j = 0; j < NP; j++) {
        int p = t*NP + j;
        px[j] = src[(b*3+0)*N + p];
        py[j] = src[(b*3+1)*N + p];
        pz[j] = src[(b*3+2)*N + p];
        sp[p] = make_float4(px[j], py[j], pz[j], 0.f);
        md[j] = 1e10f;
    }
    __syncthreads();
    int far = 0;
    for (int it = 0; it < N; it++) {
        if (t == 0) out[it] = far;
        float4 F = sp[far];
        unsigned long long best = 0ull;
        #pragma unroll
        for (int j = 0; j < NP; j++) {
            float dx = px[j]-F.x, dy = py[j]-F.y, dz = pz[j]-F.z;
            float d = dx*dx + dy*dy + dz*dz;
            md[j] = fminf(md[j], d);
            unsigned long long key =
                ((unsigned long long)__float_as_uint(md[j]) << 32) |
                (unsigned)(~(t*NP + j));
            if (key > best) best = key;
        }
        unsigned dbits = (unsigned)(best >> 32);
        unsigned m   = __reduce_max_sync(0xffffffffu, dbits);
        unsigned cand = (dbits == m) ? (unsigned)best : 0u;
        unsigned nim  = __reduce_max_sync(0xffffffffu, cand);
        if ((t & 31) == 0) skey[it & 1][t >> 5] = ((unsigned long long)m << 32) | nim;
        __syncthreads();
        unsigned long long bk = skey[it & 1][0];
        #pragma unroll
        for (int q = 1; q < 8; q++) {
            unsigned long long kq = skey[it & 1][q];
            if (kq > bk) bk = kq;
        }
        far = (int)(~(unsigned)bk);
    }
}

__global__ __launch_bounds__(256) void k_fps(const float* __restrict__ pcA,
                                             const float* __restrict__ pcB,
                                             int* __restrict__ o1, int* __restrict__ o2)
{
    __shared__ float4 sp[1024];
    __shared__ unsigned long long skey[2][8];
    int blk = blockIdx.x;
    if (blk < 8) fps_run<512, 2>(pcA, blk,     o1 + blk*512,      sp, skey);
    else         fps_run<1024,4>(pcB, blk - 8, o2 + (blk-8)*1024, sp, skey);
}

// ---------------- feature inverse norms --------------------------------------
__global__ void k_inorm(const float* __restrict__ f1, const float* __restrict__ f2,
                        float* __restrict__ o1, float* __restrict__ o2)
{
    int b = blockIdx.x, which = blockIdx.y, n = threadIdx.x;
    const float* f = which ? f2 : f1;
    float* o = which ? o2 : o1;
    float s = 0.f;
    for (int c = 0; c < 256; c++) { float v = f[(b*256+c)*256 + n]; s += v*v; }
    o[b*256+n] = 1.0f / sqrtf(s + 1e-8f);
}

// ---------------- global correlation -> flow0 --------------------------------
__global__ __launch_bounds__(256) void k_corr(const float* __restrict__ f1,
                                              const float* __restrict__ f2,
                                              const float* __restrict__ in1,
                                              const float* __restrict__ in2,
                                              const float* __restrict__ p1g,
                                              const float* __restrict__ p2g,
                                              const float* __restrict__ epsin,
                                              float* __restrict__ flow0)
{
    __shared__ float sA[32*64], sB[32*256];
    __shared__ float si1[64], si2[256], sq1[64], sq2[256];
    __shared__ float sp1[64*3], sp2[256*3];
    const int b = blockIdx.y, n0 = blockIdx.x*64, tid = threadIdx.x;
    for (int i = tid; i < 64; i += 256) {
        si1[i] = in1[b*256 + n0 + i];
        float X = p1g[(b*3+0)*256+n0+i], Y = p1g[(b*3+1)*256+n0+i], Z = p1g[(b*3+2)*256+n0+i];
        sp1[i*3] = X; sp1[i*3+1] = Y; sp1[i*3+2] = Z; sq1[i] = X*X+Y*Y+Z*Z;
    }
    for (int i = tid; i < 256; i += 256) {
        si2[i] = in2[b*256+i];
        float X = p2g[(b*3+0)*256+i], Y = p2g[(b*3+1)*256+i], Z = p2g[(b*3+2)*256+i];
        sp2[i*3] = X; sp2[i*3+1] = Y; sp2[i*3+2] = Z; sq2[i] = X*X+Y*Y+Z*Z;
    }
    const float inv_eps = 1.0f / (expf(epsin[0]) + 0.03f);
    const int ty = tid >> 5, tx = tid & 31;
    float acc[8][8];
    #pragma unroll
    for (int i = 0; i < 8; i++)
        #pragma unroll
        for (int j = 0; j < 8; j++) acc[i][j] = 0.f;
    for (int cc = 0; cc < 256; cc += 32) {
        __syncthreads();
        for (int i = tid; i < 2048; i += 256) {
            int c = i >> 6, n = i & 63;
            sA[i] = f1[(b*256 + cc + c)*256 + n0 + n];
        }
        for (int i = tid; i < 8192; i += 256) {
            int c = i >> 8, m = i & 255;
            sB[i] = f2[(b*256 + cc + c)*256 + m];
        }
        __syncthreads();
        #pragma unroll 4
        for (int c = 0; c < 32; c++) {
            float a[8], bv[8];
            #pragma unroll
            for (int i = 0; i < 8; i++) a[i] = sA[c*64 + ty*8 + i];
            #pragma unroll
            for (int j = 0; j < 8; j++) bv[j] = sB[c*256 + tx + 32*j];
            #pragma unroll
            for (int i = 0; i < 8; i++)
                #pragma unroll
                for (int j = 0; j < 8; j++) acc[i][j] = fmaf(a[i], bv[j], acc[i][j]);
        }
    }
    #pragma unroll
    for (int i = 0; i < 8; i++) {
        int n = ty*8 + i;
        float i1v = si1[n], q1 = sq1[n];
        float px = sp1[n*3], py = sp1[n*3+1], pz = sp1[n*3+2];
        float s0 = 0.f, s1 = 0.f, s2 = 0.f, s3 = 0.f;
        #pragma unroll
        for (int j = 0; j < 8; j++) {
            int m = tx + 32*j;
            float Cv = 1.0f - acc[i][j]*i1v*si2[m];
            float qx = sp2[m*3], qy = sp2[m*3+1], qz = sp2[m*3+2];
            float dm = q1 + sq2[m] - 2.0f*(px*qx + py*qy + pz*qz);
            float cv = (dm < 100.0f) ? expf(-Cv*inv_eps) : 0.0f;
            s0 += cv; s1 += cv*qx; s2 += cv*qy; s3 += cv*qz;
        }
        #pragma unroll
        for (int o = 16; o; o >>= 1) {
            s0 += __shfl_down_sync(0xffffffffu, s0, o);
            s1 += __shfl_down_sync(0xffffffffu, s1, o);
            s2 += __shfl_down_sync(0xffffffffu, s2, o);
            s3 += __shfl_down_sync(0xffffffffu, s3, o);
        }
        if (tx == 0) {
            float inv = 1.0f / (s0 + 1e-8f);
            int gn = n0 + n;
            flow0[(b*256+gn)*3+0] = s1*inv - px;
            flow0[(b*256+gn)*3+1] = s2*inv - py;
            flow0[(b*256+gn)*3+2] = s3*inv - pz;
        }
    }
}

// ---------------- feature propagation (3-NN inverse-distance) ----------------
template <int NS, int CH, bool TOUT>
__global__ __launch_bounds__(128) void k_prop(const float* __restrict__ x1,
                                              const float* __restrict__ x2,
                                              const float* __restrict__ f,
                                              float* __restrict__ o, int ND)
{
    __shared__ float4 sp[NS];
    const int b = blockIdx.y, t = threadIdx.x;
    for (int i = t; i < NS; i += 128) {
        float X = x2[(b*3+0)*NS+i], Y = x2[(b*3+1)*NS+i], Z = x2[(b*3+2)*NS+i];
        sp[i] = make_float4(X, Y, Z, X*X+Y*Y+Z*Z);
    }
    __syncthreads();
    int n = blockIdx.x*128 + t;
    float x = x1[(b*3+0)*ND+n], y = x1[(b*3+1)*ND+n], z = x1[(b*3+2)*ND+n];
    float q = x*x + y*y + z*z;
    float d0 = 1e30f, d1 = 1e30f, d2 = 1e30f;
    int i0 = 0, i1 = 0, i2 = 0;
    for (int m = 0; m < NS; m++) {
        float4 P = sp[m];
        float d = q + P.w - 2.0f*(x*P.x + y*P.y + z*P.z);
        if (d < d2) {
            if (d < d1) {
                if (d < d0) { d2=d1;i2=i1; d1=d0;i1=i0; d0=d;i0=m; }
                else        { d2=d1;i2=i1; d1=d;i1=m; }
            } else          { d2=d;i2=m; }
        }
    }
    float w0 = 1.0f/(d0+1e-8f), w1 = 1.0f/(d1+1e-8f), w2 = 1.0f/(d2+1e-8f);
    float ws = 1.0f/(w0+w1+w2); w0 *= ws; w1 *= ws; w2 *= ws;
    const float* fa = &f[((size_t)b*NS+i0)*CH];
    const float* fb = &f[((size_t)b*NS+i1)*CH];
    const float* fc = &f[((size_t)b*NS+i2)*CH];
    if (CH % 4 == 0) {
        for (int c = 0; c < CH; c += 4) {
            float4 A = *(const float4*)&fa[c];
            float4 Bq = *(const float4*)&fb[c];
            float4 Cq = *(const float4*)&fc[c];
            float o0 = w0*A.x + w1*Bq.x + w2*Cq.x;
            float o1 = w0*A.y + w1*Bq.y + w2*Cq.y;
            float o2 = w0*A.z + w1*Bq.z + w2*Cq.z;
            float o3 = w0*A.w + w1*Bq.w + w2*Cq.w;
            if (TOUT) {
                o[((size_t)b*CH+c+0)*ND+n] = o0;
                o[((size_t)b*CH+c+1)*ND+n] = o1;
                o[((size_t)b*CH+c+2)*ND+n] = o2;
                o[((size_t)b*CH+c+3)*ND+n] = o3;
            } else {
                *(float4*)&o[((size_t)b*ND+n)*CH+c] = make_float4(o0,o1,o2,o3);
            }
        }
    } else {
        for (int c = 0; c < CH; c++) {
            float ov = w0*fa[c] + w1*fb[c] + w2*fc[c];
            if (TOUT) o[((size_t)b*CH+c)*ND+n] = ov;
            else      o[((size_t)b*ND+n)*CH+c] = ov;
        }
    }
}

// ---------------- SA1 grouping: kNN-16 + gather (two-phase, vector stores) ---
__global__ __launch_bounds__(128) void k_g1(const float* __restrict__ xyz,
                                            const float* __restrict__ fl,
                                            const int* __restrict__ fps,
                                            float* __restrict__ x0)
{
    __shared__ float4 sp[512];
    __shared__ float4 scp[128];
    __shared__ int sni[128*16];
    const int b = blockIdx.y, blk = blockIdx.x, t = threadIdx.x;
    for (int i = t; i < 512; i += 128) {
        float X = xyz[(b*3+0)*512+i], Y = xyz[(b*3+1)*512+i], Z = xyz[(b*3+2)*512+i];
        sp[i] = make_float4(X, Y, Z, X*X+Y*Y+Z*Z);
    }
    __syncthreads();
    {
        int s = blk*128 + t;
        int c = fps[b*512 + s];
        float4 cp = sp[c];
        scp[t] = cp;
        float nd[16]; int ni[16];
        #pragma unroll
        for (int k = 0; k < 16; k++) { nd[k] = 1e30f; ni[k] = 0; }
        for (int m = 0; m < 512; m++) {
            float4 P = sp[m];
            float d = cp.w + P.w - 2.0f*(cp.x*P.x + cp.y*P.y + cp.z*P.z);
            if (d < nd[15]) {
                float cd = d; int ci = m;
                #pragma unroll
                for (int k = 0; k < 16; k++)
                    if (cd < nd[k]) { float td=nd[k]; int ti=ni[k]; nd[k]=cd; ni[k]=ci; cd=td; ci=ti; }
            }
        }
        #pragma unroll
        for (int k = 0; k < 16; k++) sni[t*16 + k] = ni[k];
    }
    __syncthreads();
    for (int it = 0; it < 16; it++) {
        int pair = it*128 + t;
        int cL = pair >> 4, k = pair & 15;
        int ni = sni[pair];
        float4 cp = scp[cL];
        float4 P = sp[ni];
        const float* fp = &fl[((size_t)b*512 + ni)*3];
        float f0 = fp[0], f1v = fp[1], f2v = fp[2];
        float* o = &x0[((size_t)((b*512 + blk*128 + cL)*16) + k)*8];
        *(float4*)&o[0] = make_float4(P.x-cp.x, P.y-cp.y, P.z-cp.z, f0);
        *(float4*)&o[4] = make_float4(f1v, f2v, 0.f, 0.f);
    }
}

// ---------------- SA2 grouping (two-phase, vector stores, stride 68) ---------
__global__ __launch_bounds__(128) void k_g2(const float* __restrict__ xyz,
                                            const float* __restrict__ feat,
                                            const int* __restrict__ fps,
                                            float* __restrict__ x0)
{
    __shared__ float4 sp[1024];
    __shared__ float4 scp[128];
    __shared__ int sni[128*16];
    const int b = blockIdx.y, blk = blockIdx.x, t = threadIdx.x;
    for (int i = t; i < 1024; i += 128) {
        float X = xyz[(b*3+0)*1024+i], Y = xyz[(b*3+1)*1024+i], Z = xyz[(b*3+2)*1024+i];
        sp[i] = make_float4(X, Y, Z, X*X+Y*Y+Z*Z);
    }
    __syncthreads();
    {
        int s = blk*128 + t;
        int c = fps[b*1024 + s];
        float4 cp = sp[c];
        scp[t] = cp;
        float nd[16]; int ni[16];
        #pragma unroll
        for (int k = 0; k < 16; k++) { nd[k] = 1e30f; ni[k] = 0; }
        for (int m = 0; m < 1024; m++) {
            float4 P = sp[m];
            float d = cp.w + P.w - 2.0f*(cp.x*P.x + cp.y*P.y + cp.z*P.z);
            if (d < nd[15]) {
                float cd = d; int ci = m;
                #pragma unroll
                for (int k = 0; k < 16; k++)
                    if (cd < nd[k]) { float td=nd[k]; int ti=ni[k]; nd[k]=cd; ni[k]=ci; cd=td; ci=ti; }
            }
        }
        #pragma unroll
        for (int k = 0; k < 16; k++) sni[t*16 + k] = ni[k];
    }
    __syncthreads();
    for (int it = 0; it < 16; it++) {
        int pair = it*128 + t;
        int cL = pair >> 4, k = pair & 15;
        int ni = sni[pair];
        float4 cp = scp[cL];
        float4 P = sp[ni];
        const float4* fp = (const float4*)&feat[((size_t)b*1024 + ni)*64];
        float* o = &x0[((size_t)((b*1024 + blk*128 + cL)*16) + k)*68];
        float4 v = fp[0];
        *(float4*)&o[0] = make_float4(P.x-cp.x, P.y-cp.y, P.z-cp.z, v.x);
        float4 prev = v;
        #pragma unroll
        for (int j = 1; j < 16; j++) {
            v = fp[j];
            *(float4*)&o[j*4] = make_float4(prev.y, prev.z, prev.w, v.x);
            prev = v;
        }
        *(float4*)&o[64] = make_float4(prev.y, prev.z, prev.w, 0.f);
    }
}

// ---------------- 1x1 conv (+ prev-layer IN+relu on load) + partial stats ----
template <int CIN, int XS, int COUT, int ACT>
__global__ __launch_bounds__(128) void k_conv(const float* __restrict__ x,
                                              const float* __restrict__ w,
                                              const float* __restrict__ ab,
                                              float* __restrict__ y,
                                              float* __restrict__ part,
                                              int M, int nblk)
{
    constexpr int NCG = COUT/16, RG = 128/NCG, RPT = (CIN >= 64) ? 2 : 4;
    constexpr int TR = RG*RPT, SPAD = (CIN & 1) ? CIN : CIN + 1;
    __shared__ __align__(16) float sw[CIN*COUT];
    __shared__ float sx[TR*SPAD], ss1[COUT], ss2[COUT], sa[CIN], sbb[CIN];
    const int t = threadIdx.x, blk = blockIdx.x, b = blockIdx.y;
    for (int i = t; i < CIN*COUT; i += 128) sw[i] = w[i];
    if (ACT)
        for (int i = t; i < CIN; i += 128) {
            sa[i]  = ab[(b*CIN+i)*2];
            sbb[i] = ab[(b*CIN+i)*2+1];
        }
    if (t < COUT) { ss1[t] = 0.f; ss2[t] = 0.f; }
    if (ACT) __syncthreads();
    const float* xs = x + ((size_t)b*M + (size_t)blk*TR)*XS;
    for (int i = t; i < TR*XS; i += 128) {
        int r = i / XS, c = i - r*XS;
        if (c < CIN) {
            float v = xs[i];
            if (ACT) { v = fmaf(v, sa[c], sbb[c]); v = fmaxf(v, 0.f); }
            sx[r*SPAD + c] = v;
        }
    }
    __syncthreads();
    const int rg = t / NCG, cg = t - rg*NCG;
    float acc[RPT][16];
    #pragma unroll
    for (int r = 0; r < RPT; r++)
        #pragma unroll
        for (int j = 0; j < 16; j++) acc[r][j] = 0.f;
    for (int k = 0; k < CIN; k++) {
        float xv[RPT];
        #pragma unroll
        for (int r = 0; r < RPT; r++) xv[r] = sx[(rg*RPT+r)*SPAD + k];
        const float4* wp = (const float4*)&sw[k*COUT + cg*16];
        float4 w0 = wp[0], w1 = wp[1], w2 = wp[2], w3 = wp[3];
        float wv[16] = {w0.x,w0.y,w0.z,w0.w, w1.x,w1.y,w1.z,w1.w,
                        w2.x,w2.y,w2.z,w2.w, w3.x,w3.y,w3.z,w3.w};
        #pragma unroll
        for (int r = 0; r < RPT; r++)
            #pragma unroll
            for (int j = 0; j < 16; j++) acc[r][j] = fmaf(xv[r], wv[j], acc[r][j]);
    }
    float* yp = y + ((size_t)b*M + (size_t)blk*TR)*COUT;
    float s1[16], s2[16];
    #pragma unroll
    for (int j = 0; j < 16; j++) { s1[j] = 0.f; s2[j] = 0.f; }
    #pragma unroll
    for (int r = 0; r < RPT; r++) {
        int row = rg*RPT + r;
        #pragma unroll
        for (int j = 0; j < 16; j += 4)
            *(float4*)&yp[(size_t)row*COUT + cg*16 + j] =
                make_float4(acc[r][j], acc[r][j+1], acc[r][j+2], acc[r][j+3]);
        #pragma unroll
        for (int j = 0; j < 16; j++) { s1[j] += acc[r][j]; s2[j] += acc[r][j]*acc[r][j]; }
    }
    #pragma unroll
    for (int j = 0; j < 16; j++) {
        atomicAdd(&ss1[cg*16+j], s1[j]);
        atomicAdd(&ss2[cg*16+j], s2[j]);
    }
    __syncthreads();
    if (t < COUT) {
        part[(((size_t)b*nblk + blk)*COUT + t)*2 + 0] = ss1[t];
        part[(((size_t)b*nblk + blk)*COUT + t)*2 + 1] = ss2[t];
    }
}

// ---------------- IN stats finalize ------------------------------------------
template <int COUT>
__global__ void k_fin(const float* __restrict__ part, const float* __restrict__ gamma,
                      const float* __restrict__ beta, float* __restrict__ ab,
                      int nblk, float invn)
{
    int b = blockIdx.x, c = threadIdx.x;
    float s1 = 0.f, s2 = 0.f;
    for (int i = 0; i < nblk; i++) {
        s1 += part[(((size_t)b*nblk + i)*COUT + c)*2 + 0];
        s2 += part[(((size_t)b*nblk + i)*COUT + c)*2 + 1];
    }
    float mu = s1*invn;
    float var = s2*invn - mu*mu;
    float rs = 1.0f / sqrtf(var + 1e-5f);
    float A = gamma[c]*rs;
    ab[(b*COUT+c)*2 + 0] = A;
    ab[(b*COUT+c)*2 + 1] = beta[c] - mu*A;
}

// ---------------- norm+relu+maxpool over nsample ------------------------------
template <int COUT>
__global__ void k_pool(const float* __restrict__ y, const float* __restrict__ ab,
                       float* __restrict__ o)
{
    int s = blockIdx.x, b = blockIdx.y, c = threadIdx.x, S = gridDim.x;
    float A = ab[(b*COUT+c)*2], Bc = ab[(b*COUT+c)*2+1];
    const float* yp = y + ((size_t)(b*S + s)*16)*COUT + c;
    float m = 0.f;
    #pragma unroll
    for (int k = 0; k < 16; k++) {
        float v = fmaf(yp[(size_t)k*COUT], A, Bc);
        m = fmaxf(m, v);
    }
    o[((size_t)b*S + s)*COUT + c] = m;
}

// ---------------- launch -----------------------------------------------------
extern "C" void kernel_launch(void* const* d_in, const int* in_sizes, int n_in,
                              void* d_out, int out_size)
{
    const float* pc0 = (const float*)d_in[0];
    const float* pc1 = (const float*)d_in[1];
    const float* pc2 = (const float*)d_in[2];
    const float* pc3 = (const float*)d_in[3];
    const float* q3  = (const float*)d_in[4];
    const float* f1  = (const float*)d_in[5];
    const float* f2  = (const float*)d_in[6];
    const float* eps = (const float*)d_in[7];
    const float* w10 = (const float*)d_in[8];
    const float* w11 = (const float*)d_in[9];
    const float* w12 = (const float*)d_in[10];
    const float* g10 = (const float*)d_in[11]; const float* b10 = (const float*)d_in[12];
    const float* g11 = (const float*)d_in[13]; const float* b11 = (const float*)d_in[14];
    const float* g12 = (const float*)d_in[15]; const float* b12 = (const float*)d_in[16];
    const float* w20 = (const float*)d_in[17];
    const float* w21 = (const float*)d_in[18];
    const float* w22 = (const float*)d_in[19];
    const float* g20 = (const float*)d_in[20]; const float* b20 = (const float*)d_in[21];
    const float* g21 = (const float*)d_in[22]; const float* b21 = (const float*)d_in[23];
    const float* g22 = (const float*)d_in[24]; const float* b22 = (const float*)d_in[25];
    float* out = (float*)d_out;

    void *flow0, *flow0us, *in1, *in2, *fps1, *fps2, *x0a, *ya, *yb, *yc;
    void *cf2, *cf1, *x0b, *za, *zb, *zc, *cf1o, *part, *ab;
    cudaGetSymbolAddress(&flow0, g_flow0);
    cudaGetSymbolAddress(&flow0us, g_flow0us);
    cudaGetSymbolAddress(&in1, g_in1);
    cudaGetSymbolAddress(&in2, g_in2);
    cudaGetSymbolAddress(&fps1, g_fps1);
    cudaGetSymbolAddress(&fps2, g_fps2);
    cudaGetSymbolAddress(&x0a, g_x0a);
    cudaGetSymbolAddress(&ya, g_ya);
    cudaGetSymbolAddress(&yb, g_yb);
    cudaGetSymbolAddress(&yc, g_yc);
    cudaGetSymbolAddress(&cf2, g_cf2);
    cudaGetSymbolAddress(&cf1, g_cf1);
    cudaGetSymbolAddress(&x0b, g_x0b);
    cudaGetSymbolAddress(&za, g_za);
    cudaGetSymbolAddress(&zb, g_zb);
    cudaGetSymbolAddress(&zc, g_zc);
    cudaGetSymbolAddress(&cf1o, g_cf1o);
    cudaGetSymbolAddress(&part, g_part);
    cudaGetSymbolAddress(&ab, g_ab);

    k_inorm<<<dim3(8,2), 256>>>(f1, f2, (float*)in1, (float*)in2);
    k_corr<<<dim3(4,8), 256>>>(f1, f2, (float*)in1, (float*)in2, pc3, q3, eps, (float*)flow0);
    k_prop<256,3,false><<<dim3(4,8), 128>>>(pc2, pc3, (float*)flow0, (float*)flow0us, 512);
    k_fps<<<16, 256>>>(pc2, pc1, (int*)fps1, (int*)fps2);
    k_g1<<<dim3(4,8), 128>>>(pc2, (float*)flow0us, (int*)fps1, (float*)x0a);

    k_conv<6,8,32,0><<<dim3(32,8), 128>>>((float*)x0a, w10, (float*)ab, (float*)ya, (float*)part, 8192, 32);
    k_fin<32><<<8, 32>>>((float*)part, g10, b10, (float*)ab, 32, 1.0f/8192.0f);
    k_conv<32,32,32,1><<<dim3(32,8), 128>>>((float*)ya, w11, (float*)ab, (float*)yb, (float*)part, 8192, 32);
    k_fin<32><<<8, 32>>>((float*)part, g11, b11, (float*)ab, 32, 1.0f/8192.0f);
    k_conv<32,32,64,1><<<dim3(64,8), 128>>>((float*)yb, w12, (float*)ab, (float*)yc, (float*)part, 8192, 64);
    k_fin<64><<<8, 64>>>((float*)part, g12, b12, (float*)ab, 64, 1.0f/8192.0f);
    k_pool<64><<<dim3(512,8), 64>>>((float*)yc, (float*)ab, (float*)cf2);

    k_prop<512,64,false><<<dim3(8,8), 128>>>(pc1, pc2, (float*)cf2, (float*)cf1, 1024);
    k_g2<<<dim3(8,8), 128>>>(pc1, (float*)cf1, (int*)fps2, (float*)x0b);

    k_conv<67,68,64,0><<<dim3(256,8), 128>>>((float*)x0b, w20, (float*)ab, (float*)za, (float*)part, 16384, 256);
    k_fin<64><<<8, 64>>>((float*)part, g20, b20, (float*)ab, 256, 1.0f/16384.0f);
    k_conv<64,64,64,1><<<dim3(256,8), 128>>>((float*)za, w21, (float*)ab, (float*)zb, (float*)part, 16384, 256);
    k_fin<64><<<8, 64>>>((float*)part, g21, b21, (float*)ab, 256, 1.0f/16384.0f);
    k_conv<64,64,128,1><<<dim3(512,8), 128>>>((float*)zb, w22, (float*)ab, (float*)zc, (float*)part, 16384, 512);
    k_fin<128><<<8, 128>>>((float*)part, g22, b22, (float*)ab, 512, 1.0f/16384.0f);
    k_pool<128><<<dim3(1024,8), 128>>>((float*)zc, (float*)ab, (float*)cf1o);

    k_prop<1024,128,true><<<dim3(64,8), 128>>>(pc0, pc1, (float*)cf1o, out, 8192);
}

// round 5
// speedup vs baseline: 1.9971x; 1.6274x over previous
#include <cuda_runtime.h>
#include <math.h>

// ---------------- scratch ----------------
__device__ float g_flow0 [8*256*3];
__device__ float g_flow0us[8*512*3];
__device__ float g_in1   [8*256];
__device__ float g_in2   [8*256];
__device__ int   g_fps1  [8*512];
__device__ int   g_fps2  [8*1024];
__device__ float g_x0a   [8*512*16*8];
__device__ float g_ya    [8*8192*32];
__device__ float g_yb    [8*8192*32];
__device__ float g_yc    [8*8192*64];
__device__ float g_cf2   [8*512*64];
__device__ float g_cf1   [8*1024*64];
__device__ float g_x0b   [(size_t)8*1024*16*68];
__device__ float g_za    [(size_t)8*16384*64];
__device__ float g_zb    [(size_t)8*16384*64];
__device__ float g_zc    [(size_t)8*16384*128];
__device__ float g_cf1o  [8*1024*128];
__device__ float g_part  [(size_t)8*512*128*2];
__device__ float g_ab    [8*128*2];

// ---------------- FPS (REDUX-based, 1 barrier/iter) ---------------------------
template <int N, int NP>
__device__ __forceinline__ void fps_run(const float* __restrict__ src, int b,
                                        int* __restrict__ out,
                                        float4* sp, unsigned long long (*skey)[8])
{
    int t = threadIdx.x;
    float px[NP], py[NP], pz[NP], md[NP];
    #pragma unroll
    for (int j = 0; j < NP; j++) {
        int p = t*NP + j;
        px[j] = src[(b*3+0)*N + p];
        py[j] = src[(b*3+1)*N + p];
        pz[j] = src[(b*3+2)*N + p];
        sp[p] = make_float4(px[j], py[j], pz[j], 0.f);
        md[j] = 1e10f;
    }
    __syncthreads();
    int far = 0;
    for (int it = 0; it < N; it++) {
        if (t == 0) out[it] = far;
        float4 F = sp[far];
        unsigned long long best = 0ull;
        #pragma unroll
        for (int j = 0; j < NP; j++) {
            float dx = px[j]-F.x, dy = py[j]-F.y, dz = pz[j]-F.z;
            float d = dx*dx + dy*dy + dz*dz;
            md[j] = fminf(md[j], d);
            unsigned long long key =
                ((unsigned long long)__float_as_uint(md[j]) << 32) |
                (unsigned)(~(t*NP + j));
            best = (key > best) ? key : best;
        }
        unsigned dbits = (unsigned)(best >> 32);
        unsigned m   = __reduce_max_sync(0xffffffffu, dbits);
        unsigned cand = (dbits == m) ? (unsigned)best : 0u;
        unsigned nim  = __reduce_max_sync(0xffffffffu, cand);
        if ((t & 31) == 0) skey[it & 1][t >> 5] = ((unsigned long long)m << 32) | nim;
        __syncthreads();
        unsigned long long bk = skey[it & 1][0];
        #pragma unroll
        for (int q = 1; q < 8; q++) {
            unsigned long long kq = skey[it & 1][q];
            bk = (kq > bk) ? kq : bk;
        }
        far = (int)(~(unsigned)bk);
    }
}

__global__ __launch_bounds__(256) void k_fpsA(const float* __restrict__ pc,
                                              int* __restrict__ o1)
{
    __shared__ float4 sp[512];
    __shared__ unsigned long long skey[2][8];
    fps_run<512, 2>(pc, blockIdx.x, o1 + blockIdx.x*512, sp, skey);
}

__global__ __launch_bounds__(256) void k_fpsB(const float* __restrict__ pc,
                                              int* __restrict__ o2)
{
    __shared__ float4 sp[1024];
    __shared__ unsigned long long skey[2][8];
    fps_run<1024, 4>(pc, blockIdx.x, o2 + blockIdx.x*1024, sp, skey);
}

// ---------------- feature inverse norms --------------------------------------
__global__ void k_inorm(const float* __restrict__ f1, const float* __restrict__ f2,
                        float* __restrict__ o1, float* __restrict__ o2)
{
    int b = blockIdx.x, which = blockIdx.y, n = threadIdx.x;
    const float* f = which ? f2 : f1;
    float* o = which ? o2 : o1;
    float s = 0.f;
    for (int c = 0; c < 256; c++) { float v = f[(b*256+c)*256 + n]; s += v*v; }
    o[b*256+n] = 1.0f / sqrtf(s + 1e-8f);
}

// ---------------- global correlation -> flow0 --------------------------------
__global__ __launch_bounds__(256) void k_corr(const float* __restrict__ f1,
                                              const float* __restrict__ f2,
                                              const float* __restrict__ in1,
                                              const float* __restrict__ in2,
                                              const float* __restrict__ p1g,
                                              const float* __restrict__ p2g,
                                              const float* __restrict__ epsin,
                                              float* __restrict__ flow0)
{
    __shared__ float sA[32*64], sB[32*256];
    __shared__ float si1[64], si2[256], sq1[64], sq2[256];
    __shared__ float sp1[64*3], sp2[256*3];
    const int b = blockIdx.y, n0 = blockIdx.x*64, tid = threadIdx.x;
    for (int i = tid; i < 64; i += 256) {
        si1[i] = in1[b*256 + n0 + i];
        float X = p1g[(b*3+0)*256+n0+i], Y = p1g[(b*3+1)*256+n0+i], Z = p1g[(b*3+2)*256+n0+i];
        sp1[i*3] = X; sp1[i*3+1] = Y; sp1[i*3+2] = Z; sq1[i] = X*X+Y*Y+Z*Z;
    }
    for (int i = tid; i < 256; i += 256) {
        si2[i] = in2[b*256+i];
        float X = p2g[(b*3+0)*256+i], Y = p2g[(b*3+1)*256+i], Z = p2g[(b*3+2)*256+i];
        sp2[i*3] = X; sp2[i*3+1] = Y; sp2[i*3+2] = Z; sq2[i] = X*X+Y*Y+Z*Z;
    }
    const float inv_eps = 1.0f / (expf(epsin[0]) + 0.03f);
    const int ty = tid >> 5, tx = tid & 31;
    float acc[8][8];
    #pragma unroll
    for (int i = 0; i < 8; i++)
        #pragma unroll
        for (int j = 0; j < 8; j++) acc[i][j] = 0.f;
    for (int cc = 0; cc < 256; cc += 32) {
        __syncthreads();
        for (int i = tid; i < 2048; i += 256) {
            int c = i >> 6, n = i & 63;
            sA[i] = f1[(b*256 + cc + c)*256 + n0 + n];
        }
        for (int i = tid; i < 8192; i += 256) {
            int c = i >> 8, m = i & 255;
            sB[i] = f2[(b*256 + cc + c)*256 + m];
        }
        __syncthreads();
        #pragma unroll 4
        for (int c = 0; c < 32; c++) {
            float a[8], bv[8];
            #pragma unroll
            for (int i = 0; i < 8; i++) a[i] = sA[c*64 + ty*8 + i];
            #pragma unroll
            for (int j = 0; j < 8; j++) bv[j] = sB[c*256 + tx + 32*j];
            #pragma unroll
            for (int i = 0; i < 8; i++)
                #pragma unroll
                for (int j = 0; j < 8; j++) acc[i][j] = fmaf(a[i], bv[j], acc[i][j]);
        }
    }
    #pragma unroll
    for (int i = 0; i < 8; i++) {
        int n = ty*8 + i;
        float i1v = si1[n], q1 = sq1[n];
        float px = sp1[n*3], py = sp1[n*3+1], pz = sp1[n*3+2];
        float s0 = 0.f, s1 = 0.f, s2 = 0.f, s3 = 0.f;
        #pragma unroll
        for (int j = 0; j < 8; j++) {
            int m = tx + 32*j;
            float Cv = 1.0f - acc[i][j]*i1v*si2[m];
            float qx = sp2[m*3], qy = sp2[m*3+1], qz = sp2[m*3+2];
            float dm = q1 + sq2[m] - 2.0f*(px*qx + py*qy + pz*qz);
            float cv = (dm < 100.0f) ? expf(-Cv*inv_eps) : 0.0f;
            s0 += cv; s1 += cv*qx; s2 += cv*qy; s3 += cv*qz;
        }
        #pragma unroll
        for (int o = 16; o; o >>= 1) {
            s0 += __shfl_down_sync(0xffffffffu, s0, o);
            s1 += __shfl_down_sync(0xffffffffu, s1, o);
            s2 += __shfl_down_sync(0xffffffffu, s2, o);
            s3 += __shfl_down_sync(0xffffffffu, s3, o);
        }
        if (tx == 0) {
            float inv = 1.0f / (s0 + 1e-8f);
            int gn = n0 + n;
            flow0[(b*256+gn)*3+0] = s1*inv - px;
            flow0[(b*256+gn)*3+1] = s2*inv - py;
            flow0[(b*256+gn)*3+2] = s3*inv - pz;
        }
    }
}

// ---------------- feature propagation (branchless 3-NN) -----------------------
template <int NS, int CH, bool TOUT>
__global__ __launch_bounds__(128) void k_prop(const float* __restrict__ x1,
                                              const float* __restrict__ x2,
                                              const float* __restrict__ f,
                                              float* __restrict__ o, int ND)
{
    __shared__ float4 sp[NS];
    const int b = blockIdx.y, t = threadIdx.x;
    for (int i = t; i < NS; i += 128) {
        float X = x2[(b*3+0)*NS+i], Y = x2[(b*3+1)*NS+i], Z = x2[(b*3+2)*NS+i];
        sp[i] = make_float4(X, Y, Z, X*X+Y*Y+Z*Z);
    }
    __syncthreads();
    int n = blockIdx.x*128 + t;
    float x = x1[(b*3+0)*ND+n], y = x1[(b*3+1)*ND+n], z = x1[(b*3+2)*ND+n];
    float q = x*x + y*y + z*z;
    float d0 = 1e30f, d1 = 1e30f, d2 = 1e30f;
    int i0 = 0, i1 = 0, i2 = 0;
    #pragma unroll 4
    for (int m = 0; m < NS; m++) {
        float4 P = sp[m];
        float d = q + P.w - 2.0f*(x*P.x + y*P.y + z*P.z);
        bool b0 = d < d0, b1 = d < d1, b2 = d < d2;
        d2 = b1 ? d1 : (b2 ? d : d2);
        i2 = b1 ? i1 : (b2 ? m : i2);
        d1 = b0 ? d0 : (b1 ? d : d1);
        i1 = b0 ? i0 : (b1 ? m : i1);
        d0 = b0 ? d : d0;
        i0 = b0 ? m : i0;
    }
    float w0 = 1.0f/(d0+1e-8f), w1 = 1.0f/(d1+1e-8f), w2 = 1.0f/(d2+1e-8f);
    float ws = 1.0f/(w0+w1+w2); w0 *= ws; w1 *= ws; w2 *= ws;
    const float* fa = &f[((size_t)b*NS+i0)*CH];
    const float* fb = &f[((size_t)b*NS+i1)*CH];
    const float* fc = &f[((size_t)b*NS+i2)*CH];
    if (CH % 4 == 0) {
        for (int c = 0; c < CH; c += 4) {
            float4 A = *(const float4*)&fa[c];
            float4 Bq = *(const float4*)&fb[c];
            float4 Cq = *(const float4*)&fc[c];
            float o0 = w0*A.x + w1*Bq.x + w2*Cq.x;
            float o1 = w0*A.y + w1*Bq.y + w2*Cq.y;
            float o2 = w0*A.z + w1*Bq.z + w2*Cq.z;
            float o3 = w0*A.w + w1*Bq.w + w2*Cq.w;
            if (TOUT) {
                o[((size_t)b*CH+c+0)*ND+n] = o0;
                o[((size_t)b*CH+c+1)*ND+n] = o1;
                o[((size_t)b*CH+c+2)*ND+n] = o2;
                o[((size_t)b*CH+c+3)*ND+n] = o3;
            } else {
                *(float4*)&o[((size_t)b*ND+n)*CH+c] = make_float4(o0,o1,o2,o3);
            }
        }
    } else {
        for (int c = 0; c < CH; c++) {
            float ov = w0*fa[c] + w1*fb[c] + w2*fc[c];
            if (TOUT) o[((size_t)b*CH+c)*ND+n] = ov;
            else      o[((size_t)b*ND+n)*CH+c] = ov;
        }
    }
}

// ---------------- SA1 grouping: kNN-16 + gather (two-phase, vector stores) ---
__global__ __launch_bounds__(128) void k_g1(const float* __restrict__ xyz,
                                            const float* __restrict__ fl,
                                            const int* __restrict__ fps,
                                            float* __restrict__ x0)
{
    __shared__ float4 sp[512];
    __shared__ float4 scp[128];
    __shared__ int sni[128*16];
    const int b = blockIdx.y, blk = blockIdx.x, t = threadIdx.x;
    for (int i = t; i < 512; i += 128) {
        float X = xyz[(b*3+0)*512+i], Y = xyz[(b*3+1)*512+i], Z = xyz[(b*3+2)*512+i];
        sp[i] = make_float4(X, Y, Z, X*X+Y*Y+Z*Z);
    }
    __syncthreads();
    {
        int s = blk*128 + t;
        int c = fps[b*512 + s];
        float4 cp = sp[c];
        scp[t] = cp;
        float nd[16]; int ni[16];
        #pragma unroll
        for (int k = 0; k < 16; k++) { nd[k] = 1e30f; ni[k] = 0; }
        for (int m = 0; m < 512; m++) {
            float4 P = sp[m];
            float d = cp.w + P.w - 2.0f*(cp.x*P.x + cp.y*P.y + cp.z*P.z);
            if (d < nd[15]) {
                float cd = d; int ci = m;
                #pragma unroll
                for (int k = 0; k < 16; k++)
                    if (cd < nd[k]) { float td=nd[k]; int ti=ni[k]; nd[k]=cd; ni[k]=ci; cd=td; ci=ti; }
            }
        }
        #pragma unroll
        for (int k = 0; k < 16; k++) sni[t*16 + k] = ni[k];
    }
    __syncthreads();
    for (int it = 0; it < 16; it++) {
        int pair = it*128 + t;
        int cL = pair >> 4, k = pair & 15;
        int ni = sni[pair];
        float4 cp = scp[cL];
        float4 P = sp[ni];
        const float* fp = &fl[((size_t)b*512 + ni)*3];
        float f0 = fp[0], f1v = fp[1], f2v = fp[2];
        float* o = &x0[((size_t)((b*512 + blk*128 + cL)*16) + k)*8];
        *(float4*)&o[0] = make_float4(P.x-cp.x, P.y-cp.y, P.z-cp.z, f0);
        *(float4*)&o[4] = make_float4(f1v, f2v, 0.f, 0.f);
    }
}

// ---------------- SA2 grouping (two-phase, vector stores, stride 68) ---------
__global__ __launch_bounds__(128) void k_g2(const float* __restrict__ xyz,
                                            const float* __restrict__ feat,
                                            const int* __restrict__ fps,
                                            float* __restrict__ x0)
{
    __shared__ float4 sp[1024];
    __shared__ float4 scp[128];
    __shared__ int sni[128*16];
    const int b = blockIdx.y, blk = blockIdx.x, t = threadIdx.x;
    for (int i = t; i < 1024; i += 128) {
        float X = xyz[(b*3+0)*1024+i], Y = xyz[(b*3+1)*1024+i], Z = xyz[(b*3+2)*1024+i];
        sp[i] = make_float4(X, Y, Z, X*X+Y*Y+Z*Z);
    }
    __syncthreads();
    {
        int s = blk*128 + t;
        int c = fps[b*1024 + s];
        float4 cp = sp[c];
        scp[t] = cp;
        float nd[16]; int ni[16];
        #pragma unroll
        for (int k = 0; k < 16; k++) { nd[k] = 1e30f; ni[k] = 0; }
        for (int m = 0; m < 1024; m++) {
            float4 P = sp[m];
            float d = cp.w + P.w - 2.0f*(cp.x*P.x + cp.y*P.y + cp.z*P.z);
            if (d < nd[15]) {
                float cd = d; int ci = m;
                #pragma unroll
                for (int k = 0; k < 16; k++)
                    if (cd < nd[k]) { float td=nd[k]; int ti=ni[k]; nd[k]=cd; ni[k]=ci; cd=td; ci=ti; }
            }
        }
        #pragma unroll
        for (int k = 0; k < 16; k++) sni[t*16 + k] = ni[k];
    }
    __syncthreads();
    for (int it = 0; it < 16; it++) {
        int pair = it*128 + t;
        int cL = pair >> 4, k = pair & 15;
        int ni = sni[pair];
        float4 cp = scp[cL];
        float4 P = sp[ni];
        const float4* fp = (const float4*)&feat[((size_t)b*1024 + ni)*64];
        float* o = &x0[((size_t)((b*1024 + blk*128 + cL)*16) + k)*68];
        float4 v = fp[0];
        *(float4*)&o[0] = make_float4(P.x-cp.x, P.y-cp.y, P.z-cp.z, v.x);
        float4 prev = v;
        #pragma unroll
        for (int j = 1; j < 16; j++) {
            v = fp[j];
            *(float4*)&o[j*4] = make_float4(prev.y, prev.z, prev.w, v.x);
            prev = v;
        }
        *(float4*)&o[64] = make_float4(prev.y, prev.z, prev.w, 0.f);
    }
}

// ---------------- 1x1 conv (+ prev-layer IN+relu on load) + partial stats ----
template <int CIN, int XS, int COUT, int ACT>
__global__ __launch_bounds__(128) void k_conv(const float* __restrict__ x,
                                              const float* __restrict__ w,
                                              const float* __restrict__ ab,
                                              float* __restrict__ y,
                                              float* __restrict__ part,
                                              int M, int nblk)
{
    constexpr int NCG = COUT/16, RG = 128/NCG, RPT = (CIN >= 64) ? 2 : 4;
    constexpr int TR = RG*RPT, SPAD = (CIN & 1) ? CIN : CIN + 1;
    __shared__ __align__(16) float sw[CIN*COUT];
    __shared__ float sx[TR*SPAD], sa[CIN], sbb[CIN];
    __shared__ float sred[4][2*COUT];
    const int t = threadIdx.x, blk = blockIdx.x, b = blockIdx.y;
    for (int i = t; i < CIN*COUT; i += 128) sw[i] = w[i];
    if (ACT)
        for (int i = t; i < CIN; i += 128) {
            sa[i]  = ab[(b*CIN+i)*2];
            sbb[i] = ab[(b*CIN+i)*2+1];
        }
    if (ACT) __syncthreads();
    const float* xs = x + ((size_t)b*M + (size_t)blk*TR)*XS;
    for (int i = t; i < TR*XS; i += 128) {
        int r = i / XS, c = i - r*XS;
        if (c < CIN) {
            float v = xs[i];
            if (ACT) { v = fmaf(v, sa[c], sbb[c]); v = fmaxf(v, 0.f); }
            sx[r*SPAD + c] = v;
        }
    }
    __syncthreads();
    const int rg = t / NCG, cg = t - rg*NCG;
    float acc[RPT][16];
    #pragma unroll
    for (int r = 0; r < RPT; r++)
        #pragma unroll
        for (int j = 0; j < 16; j++) acc[r][j] = 0.f;
    for (int k = 0; k < CIN; k++) {
        float xv[RPT];
        #pragma unroll
        for (int r = 0; r < RPT; r++) xv[r] = sx[(rg*RPT+r)*SPAD + k];
        const float4* wp = (const float4*)&sw[k*COUT + cg*16];
        float4 w0 = wp[0], w1 = wp[1], w2 = wp[2], w3 = wp[3];
        float wv[16] = {w0.x,w0.y,w0.z,w0.w, w1.x,w1.y,w1.z,w1.w,
                        w2.x,w2.y,w2.z,w2.w, w3.x,w3.y,w3.z,w3.w};
        #pragma unroll
        for (int r = 0; r < RPT; r++)
            #pragma unroll
            for (int j = 0; j < 16; j++) acc[r][j] = fmaf(xv[r], wv[j], acc[r][j]);
    }
    float* yp = y + ((size_t)b*M + (size_t)blk*TR)*COUT;
    float s1[16], s2[16];
    #pragma unroll
    for (int j = 0; j < 16; j++) { s1[j] = 0.f; s2[j] = 0.f; }
    #pragma unroll
    for (int r = 0; r < RPT; r++) {
        int row = rg*RPT + r;
        #pragma unroll
        for (int j = 0; j < 16; j += 4)
            *(float4*)&yp[(size_t)row*COUT + cg*16 + j] =
                make_float4(acc[r][j], acc[r][j+1], acc[r][j+2], acc[r][j+3]);
        #pragma unroll
        for (int j = 0; j < 16; j++) { s1[j] += acc[r][j]; s2[j] += acc[r][j]*acc[r][j]; }
    }
    // cross-lane reduction over row-groups sharing cg (lane%NCG == cg, NCG | 32)
    #pragma unroll
    for (int off = NCG; off < 32; off <<= 1) {
        #pragma unroll
        for (int j = 0; j < 16; j++) {
            s1[j] += __shfl_xor_sync(0xffffffffu, s1[j], off);
            s2[j] += __shfl_xor_sync(0xffffffffu, s2[j], off);
        }
    }
    const int lane = t & 31, wp2 = t >> 5;
    if (lane < NCG) {
        #pragma unroll
        for (int j = 0; j < 16; j++) {
            sred[wp2][lane*16 + j]        = s1[j];
            sred[wp2][COUT + lane*16 + j] = s2[j];
        }
    }
    __syncthreads();
    if (t < COUT) {
        float a1 = sred[0][t] + sred[1][t] + sred[2][t] + sred[3][t];
        float a2 = sred[0][COUT+t] + sred[1][COUT+t] + sred[2][COUT+t] + sred[3][COUT+t];
        part[(((size_t)b*nblk + blk)*COUT + t)*2 + 0] = a1;
        part[(((size_t)b*nblk + blk)*COUT + t)*2 + 1] = a2;
    }
}

// ---------------- IN stats finalize (warp per channel) ------------------------
template <int COUT>
__global__ __launch_bounds__(256) void k_fin(const float* __restrict__ part,
                                             const float* __restrict__ gamma,
                                             const float* __restrict__ beta,
                                             float* __restrict__ ab,
                                             int nblk, float invn)
{
    int b = blockIdx.x;
    int wp = threadIdx.x >> 5, lane = threadIdx.x & 31;
    int c = blockIdx.y*8 + wp;
    float s1 = 0.f, s2 = 0.f;
    for (int i = lane; i < nblk; i += 32) {
        const float* p = &part[(((size_t)b*nblk + i)*COUT + c)*2];
        s1 += p[0]; s2 += p[1];
    }
    #pragma unroll
    for (int o = 16; o; o >>= 1) {
        s1 += __shfl_down_sync(0xffffffffu, s1, o);
        s2 += __shfl_down_sync(0xffffffffu, s2, o);
    }
    if (lane == 0) {
        float mu = s1*invn;
        float var = s2*invn - mu*mu;
        float rs = 1.0f / sqrtf(var + 1e-5f);
        float A = gamma[c]*rs;
        ab[(b*COUT+c)*2 + 0] = A;
        ab[(b*COUT+c)*2 + 1] = beta[c] - mu*A;
    }
}

// ---------------- norm+relu+maxpool over nsample ------------------------------
template <int COUT>
__global__ void k_pool(const float* __restrict__ y, const float* __restrict__ ab,
                       float* __restrict__ o)
{
    int s = blockIdx.x, b = blockIdx.y, c = threadIdx.x, S = gridDim.x;
    float A = ab[(b*COUT+c)*2], Bc = ab[(b*COUT+c)*2+1];
    const float* yp = y + ((size_t)(b*S + s)*16)*COUT + c;
    float m = 0.f;
    #pragma unroll
    for (int k = 0; k < 16; k++) {
        float v = fmaf(yp[(size_t)k*COUT], A, Bc);
        m = fmaxf(m, v);
    }
    o[((size_t)b*S + s)*COUT + c] = m;
}

// ---------------- launch -----------------------------------------------------
extern "C" void kernel_launch(void* const* d_in, const int* in_sizes, int n_in,
                              void* d_out, int out_size)
{
    const float* pc0 = (const float*)d_in[0];
    const float* pc1 = (const float*)d_in[1];
    const float* pc2 = (const float*)d_in[2];
    const float* pc3 = (const float*)d_in[3];
    const float* q3  = (const float*)d_in[4];
    const float* f1  = (const float*)d_in[5];
    const float* f2  = (const float*)d_in[6];
    const float* eps = (const float*)d_in[7];
    const float* w10 = (const float*)d_in[8];
    const float* w11 = (const float*)d_in[9];
    const float* w12 = (const float*)d_in[10];
    const float* g10 = (const float*)d_in[11]; const float* b10 = (const float*)d_in[12];
    const float* g11 = (const float*)d_in[13]; const float* b11 = (const float*)d_in[14];
    const float* g12 = (const float*)d_in[15]; const float* b12 = (const float*)d_in[16];
    const float* w20 = (const float*)d_in[17];
    const float* w21 = (const float*)d_in[18];
    const float* w22 = (const float*)d_in[19];
    const float* g20 = (const float*)d_in[20]; const float* b20 = (const float*)d_in[21];
    const float* g21 = (const float*)d_in[22]; const float* b21 = (const float*)d_in[23];
    const float* g22 = (const float*)d_in[24]; const float* b22 = (const float*)d_in[25];
    float* out = (float*)d_out;

    void *flow0, *flow0us, *in1, *in2, *fps1, *fps2, *x0a, *ya, *yb, *yc;
    void *cf2, *cf1, *x0b, *za, *zb, *zc, *cf1o, *part, *ab;
    cudaGetSymbolAddress(&flow0, g_flow0);
    cudaGetSymbolAddress(&flow0us, g_flow0us);
    cudaGetSymbolAddress(&in1, g_in1);
    cudaGetSymbolAddress(&in2, g_in2);
    cudaGetSymbolAddress(&fps1, g_fps1);
    cudaGetSymbolAddress(&fps2, g_fps2);
    cudaGetSymbolAddress(&x0a, g_x0a);
    cudaGetSymbolAddress(&ya, g_ya);
    cudaGetSymbolAddress(&yb, g_yb);
    cudaGetSymbolAddress(&yc, g_yc);
    cudaGetSymbolAddress(&cf2, g_cf2);
    cudaGetSymbolAddress(&cf1, g_cf1);
    cudaGetSymbolAddress(&x0b, g_x0b);
    cudaGetSymbolAddress(&za, g_za);
    cudaGetSymbolAddress(&zb, g_zb);
    cudaGetSymbolAddress(&zc, g_zc);
    cudaGetSymbolAddress(&cf1o, g_cf1o);
    cudaGetSymbolAddress(&part, g_part);
    cudaGetSymbolAddress(&ab, g_ab);

    // side stream for FPS overlap (fork/join with events; non-blocking to
    // avoid legacy-stream implicit sync). Handles are created fresh per call
    // and intentionally not destroyed mid-capture.
    cudaStream_t s2;
    cudaStreamCreateWithFlags(&s2, cudaStreamNonBlocking);
    cudaEvent_t eF, e1, e2;
    cudaEventCreateWithFlags(&eF, cudaEventDisableTiming);
    cudaEventCreateWithFlags(&e1, cudaEventDisableTiming);
    cudaEventCreateWithFlags(&e2, cudaEventDisableTiming);

    cudaEventRecord(eF, 0);
    cudaStreamWaitEvent(s2, eF, 0);
    k_fpsA<<<8, 256, 0, s2>>>(pc2, (int*)fps1);                                   // [0]
    k_inorm<<<dim3(8,2), 256>>>(f1, f2, (float*)in1, (float*)in2);                // [1]
    k_corr<<<dim3(4,8), 256>>>(f1, f2, (float*)in1, (float*)in2, pc3, q3, eps, (float*)flow0); // [2]
    k_prop<256,3,false><<<dim3(4,8), 128>>>(pc2, pc3, (float*)flow0, (float*)flow0us, 512);    // [3] probe
    cudaEventRecord(e1, s2);
    k_fpsB<<<8, 256, 0, s2>>>(pc1, (int*)fps2);                                   // [4]
    cudaEventRecord(e2, s2);

    cudaStreamWaitEvent(0, e1, 0);
    k_g1<<<dim3(4,8), 128>>>(pc2, (float*)flow0us, (int*)fps1, (float*)x0a);

    k_conv<6,8,32,0><<<dim3(32,8), 128>>>((float*)x0a, w10, (float*)ab, (float*)ya, (float*)part, 8192, 32);
    k_fin<32><<<dim3(8,4), 256>>>((float*)part, g10, b10, (float*)ab, 32, 1.0f/8192.0f);
    k_conv<32,32,32,1><<<dim3(32,8), 128>>>((float*)ya, w11, (float*)ab, (float*)yb, (float*)part, 8192, 32);
    k_fin<32><<<dim3(8,4), 256>>>((float*)part, g11, b11, (float*)ab, 32, 1.0f/8192.0f);
    k_conv<32,32,64,1><<<dim3(64,8), 128>>>((float*)yb, w12, (float*)ab, (float*)yc, (float*)part, 8192, 64);
    k_fin<64><<<dim3(8,8), 256>>>((float*)part, g12, b12, (float*)ab, 64, 1.0f/8192.0f);
    k_pool<64><<<dim3(512,8), 64>>>((float*)yc, (float*)ab, (float*)cf2);

    k_prop<512,64,false><<<dim3(8,8), 128>>>(pc1, pc2, (float*)cf2, (float*)cf1, 1024);
    cudaStreamWaitEvent(0, e2, 0);
    k_g2<<<dim3(8,8), 128>>>(pc1, (float*)cf1, (int*)fps2, (float*)x0b);

    k_conv<67,68,64,0><<<dim3(256,8), 128>>>((float*)x0b, w20, (float*)ab, (float*)za, (float*)part, 16384, 256);
    k_fin<64><<<dim3(8,8), 256>>>((float*)part, g20, b20, (float*)ab, 256, 1.0f/16384.0f);
    k_conv<64,64,64,1><<<dim3(256,8), 128>>>((float*)za, w21, (float*)ab, (float*)zb, (float*)part, 16384, 256);
    k_fin<64><<<dim3(8,8), 256>>>((float*)part, g21, b21, (float*)ab, 256, 1.0f/16384.0f);
    k_conv<64,64,128,1><<<dim3(512,8), 128>>>((float*)zb, w22, (float*)ab, (float*)zc, (float*)part, 16384, 512);
    k_fin<128><<<dim3(8,16), 256>>>((float*)part, g22, b22, (float*)ab, 512, 1.0f/16384.0f);
    k_pool<128><<<dim3(1024,8), 128>>>((float*)zc, (float*)ab, (float*)cf1o);

    k_prop<1024,128,true><<<dim3(64,8), 128>>>(pc0, pc1, (float*)cf1o, out, 8192);
}

// round 10
// speedup vs baseline: 1.9998x; 1.0014x over previous
#include <cuda_runtime.h>
#include <math.h>

// ---------------- scratch ----------------
__device__ float g_flow0 [8*256*3];
__device__ float g_flow0us[8*512*3];
__device__ float g_in1   [8*256];
__device__ float g_in2   [8*256];
__device__ int   g_fps1  [8*512];
__device__ int   g_fps2  [8*1024];
__device__ float g_x0a   [8*512*16*8];
__device__ float g_ya    [8*8192*32];
__device__ float g_yb    [8*8192*32];
__device__ float g_yc    [8*8192*64];     // reused: SA1 pooled max/min
__device__ float g_cf2   [8*512*64];
__device__ float g_cf1   [8*1024*64];
__device__ float g_x0b   [(size_t)8*1024*16*68];
__device__ float g_za    [(size_t)8*16384*64];
__device__ float g_zb    [(size_t)8*16384*64];
__device__ float g_zc    [(size_t)8*16384*128]; // reused: SA2 pooled max/min
__device__ float g_cf1o  [8*1024*128];
__device__ float g_part  [(size_t)8*512*128*2];
__device__ float g_ab    [8*128*2];

// ---------------- FPS (REDUX-based, 1 barrier/iter) ---------------------------
template <int N, int NP>
__device__ __forceinline__ void fps_run(const float* __restrict__ src, int b,
                                        int* __restrict__ out,
                                        float4* sp, unsigned long long (*skey)[8])
{
    int t = threadIdx.x;
    float px[NP], py[NP], pz[NP], md[NP];
    #pragma unroll
    for (int j = 0; j < NP; j++) {
        int p = t*NP + j;
        px[j] = src[(b*3+0)*N + p];
        py[j] = src[(b*3+1)*N + p];
        pz[j] = src[(b*3+2)*N + p];
        sp[p] = make_float4(px[j], py[j], pz[j], 0.f);
        md[j] = 1e10f;
    }
    __syncthreads();
    int far = 0;
    for (int it = 0; it < N; it++) {
        if (t == 0) out[it] = far;
        float4 F = sp[far];
        unsigned long long best = 0ull;
        #pragma unroll
        for (int j = 0; j < NP; j++) {
            float dx = px[j]-F.x, dy = py[j]-F.y, dz = pz[j]-F.z;
            float d = dx*dx + dy*dy + dz*dz;
            md[j] = fminf(md[j], d);
            unsigned long long key =
                ((unsigned long long)__float_as_uint(md[j]) << 32) |
                (unsigned)(~(t*NP + j));
            best = (key > best) ? key : best;
        }
        unsigned dbits = (unsigned)(best >> 32);
        unsigned m   = __reduce_max_sync(0xffffffffu, dbits);
        unsigned cand = (dbits == m) ? (unsigned)best : 0u;
        unsigned nim  = __reduce_max_sync(0xffffffffu, cand);
        if ((t & 31) == 0) skey[it & 1][t >> 5] = ((unsigned long long)m << 32) | nim;
        __syncthreads();
        unsigned long long bk = skey[it & 1][0];
        #pragma unroll
        for (int q = 1; q < 8; q++) {
            unsigned long long kq = skey[it & 1][q];
            bk = (kq > bk) ? kq : bk;
        }
        far = (int)(~(unsigned)bk);
    }
}

__global__ __launch_bounds__(256) void k_fpsA(const float* __restrict__ pc,
                                              int* __restrict__ o1)
{
    __shared__ float4 sp[512];
    __shared__ unsigned long long skey[2][8];
    fps_run<512, 2>(pc, blockIdx.x, o1 + blockIdx.x*512, sp, skey);
}

__global__ __launch_bounds__(256) void k_fpsB(const float* __restrict__ pc,
                                              int* __restrict__ o2)
{
    __shared__ float4 sp[1024];
    __shared__ unsigned long long skey[2][8];
    fps_run<1024, 4>(pc, blockIdx.x, o2 + blockIdx.x*1024, sp, skey);
}

// ---------------- feature inverse norms --------------------------------------
__global__ void k_inorm(const float* __restrict__ f1, const float* __restrict__ f2,
                        float* __restrict__ o1, float* __restrict__ o2)
{
    int b = blockIdx.x, which = blockIdx.y, n = threadIdx.x;
    const float* f = which ? f2 : f1;
    float* o = which ? o2 : o1;
    float s = 0.f;
    for (int c = 0; c < 256; c++) { float v = f[(b*256+c)*256 + n]; s += v*v; }
    o[b*256+n] = 1.0f / sqrtf(s + 1e-8f);
}

// ---------------- global correlation -> flow0 --------------------------------
__global__ __launch_bounds__(256) void k_corr(const float* __restrict__ f1,
                                              const float* __restrict__ f2,
                                              const float* __restrict__ in1,
                                              const float* __restrict__ in2,
                                              const float* __restrict__ p1g,
                                              const float* __restrict__ p2g,
                                              const float* __restrict__ epsin,
                                              float* __restrict__ flow0)
{
    __shared__ float sA[32*64], sB[32*256];
    __shared__ float si1[64], si2[256], sq1[64], sq2[256];
    __shared__ float sp1[64*3], sp2[256*3];
    const int b = blockIdx.y, n0 = blockIdx.x*64, tid = threadIdx.x;
    for (int i = tid; i < 64; i += 256) {
        si1[i] = in1[b*256 + n0 + i];
        float X = p1g[(b*3+0)*256+n0+i], Y = p1g[(b*3+1)*256+n0+i], Z = p1g[(b*3+2)*256+n0+i];
        sp1[i*3] = X; sp1[i*3+1] = Y; sp1[i*3+2] = Z; sq1[i] = X*X+Y*Y+Z*Z;
    }
    for (int i = tid; i < 256; i += 256) {
        si2[i] = in2[b*256+i];
        float X = p2g[(b*3+0)*256+i], Y = p2g[(b*3+1)*256+i], Z = p2g[(b*3+2)*256+i];
        sp2[i*3] = X; sp2[i*3+1] = Y; sp2[i*3+2] = Z; sq2[i] = X*X+Y*Y+Z*Z;
    }
    const float inv_eps = 1.0f / (expf(epsin[0]) + 0.03f);
    const int ty = tid >> 5, tx = tid & 31;
    float acc[8][8];
    #pragma unroll
    for (int i = 0; i < 8; i++)
        #pragma unroll
        for (int j = 0; j < 8; j++) acc[i][j] = 0.f;
    for (int cc = 0; cc < 256; cc += 32) {
        __syncthreads();
        for (int i = tid; i < 2048; i += 256) {
            int c = i >> 6, n = i & 63;
            sA[i] = f1[(b*256 + cc + c)*256 + n0 + n];
        }
        for (int i = tid; i < 8192; i += 256) {
            int c = i >> 8, m = i & 255;
            sB[i] = f2[(b*256 + cc + c)*256 + m];
        }
        __syncthreads();
        #pragma unroll 4
        for (int c = 0; c < 32; c++) {
            float a[8], bv[8];
            #pragma unroll
            for (int i = 0; i < 8; i++) a[i] = sA[c*64 + ty*8 + i];
            #pragma unroll
            for (int j = 0; j < 8; j++) bv[j] = sB[c*256 + tx + 32*j];
            #pragma unroll
            for (int i = 0; i < 8; i++)
                #pragma unroll
                for (int j = 0; j < 8; j++) acc[i][j] = fmaf(a[i], bv[j], acc[i][j]);
        }
    }
    #pragma unroll
    for (int i = 0; i < 8; i++) {
        int n = ty*8 + i;
        float i1v = si1[n], q1 = sq1[n];
        float px = sp1[n*3], py = sp1[n*3+1], pz = sp1[n*3+2];
        float s0 = 0.f, s1 = 0.f, s2 = 0.f, s3 = 0.f;
        #pragma unroll
        for (int j = 0; j < 8; j++) {
            int m = tx + 32*j;
            float Cv = 1.0f - acc[i][j]*i1v*si2[m];
            float qx = sp2[m*3], qy = sp2[m*3+1], qz = sp2[m*3+2];
            float dm = q1 + sq2[m] - 2.0f*(px*qx + py*qy + pz*qz);
            float cv = (dm < 100.0f) ? expf(-Cv*inv_eps) : 0.0f;
            s0 += cv; s1 += cv*qx; s2 += cv*qy; s3 += cv*qz;
        }
        #pragma unroll
        for (int o = 16; o; o >>= 1) {
            s0 += __shfl_down_sync(0xffffffffu, s0, o);
            s1 += __shfl_down_sync(0xffffffffu, s1, o);
            s2 += __shfl_down_sync(0xffffffffu, s2, o);
            s3 += __shfl_down_sync(0xffffffffu, s3, o);
        }
        if (tx == 0) {
            float inv = 1.0f / (s0 + 1e-8f);
            int gn = n0 + n;
            flow0[(b*256+gn)*3+0] = s1*inv - px;
            flow0[(b*256+gn)*3+1] = s2*inv - py;
            flow0[(b*256+gn)*3+2] = s3*inv - pz;
        }
    }
}

// ---------------- feature propagation (exact branchless 3-NN) -----------------
template <int NS, int CH, bool TOUT>
__global__ __launch_bounds__(128) void k_prop(const float* __restrict__ x1,
                                              const float* __restrict__ x2,
                                              const float* __restrict__ f,
                                              float* __restrict__ o, int ND)
{
    __shared__ float4 sp[NS];
    const int b = blockIdx.y, t = threadIdx.x;
    for (int i = t; i < NS; i += 128) {
        float X = x2[(b*3+0)*NS+i], Y = x2[(b*3+1)*NS+i], Z = x2[(b*3+2)*NS+i];
        sp[i] = make_float4(X, Y, Z, X*X+Y*Y+Z*Z);
    }
    __syncthreads();
    int n = blockIdx.x*128 + t;
    float x = x1[(b*3+0)*ND+n], y = x1[(b*3+1)*ND+n], z = x1[(b*3+2)*ND+n];
    float q = x*x + y*y + z*z;
    float d0 = 1e30f, d1 = 1e30f, d2 = 1e30f;
    int i0 = 0, i1 = 0, i2 = 0;
    #pragma unroll 4
    for (int m = 0; m < NS; m++) {
        float4 P = sp[m];
        float d = q + P.w - 2.0f*(x*P.x + y*P.y + z*P.z);
        bool b0 = d < d0, b1 = d < d1, b2 = d < d2;
        d2 = b1 ? d1 : (b2 ? d : d2);
        i2 = b1 ? i1 : (b2 ? m : i2);
        d1 = b0 ? d0 : (b1 ? d : d1);
        i1 = b0 ? i0 : (b1 ? m : i1);
        d0 = b0 ? d : d0;
        i0 = b0 ? m : i0;
    }
    float w0 = 1.0f/(d0+1e-8f), w1 = 1.0f/(d1+1e-8f), w2 = 1.0f/(d2+1e-8f);
    float ws = 1.0f/(w0+w1+w2); w0 *= ws; w1 *= ws; w2 *= ws;
    const float* fa = &f[((size_t)b*NS+i0)*CH];
    const float* fb = &f[((size_t)b*NS+i1)*CH];
    const float* fc = &f[((size_t)b*NS+i2)*CH];
    if (CH % 4 == 0) {
        for (int c = 0; c < CH; c += 4) {
            float4 A = *(const float4*)&fa[c];
            float4 Bq = *(const float4*)&fb[c];
            float4 Cq = *(const float4*)&fc[c];
            float o0 = w0*A.x + w1*Bq.x + w2*Cq.x;
            float o1 = w0*A.y + w1*Bq.y + w2*Cq.y;
            float o2 = w0*A.z + w1*Bq.z + w2*Cq.z;
            float o3 = w0*A.w + w1*Bq.w + w2*Cq.w;
            if (TOUT) {
                o[((size_t)b*CH+c+0)*ND+n] = o0;
                o[((size_t)b*CH+c+1)*ND+n] = o1;
                o[((size_t)b*CH+c+2)*ND+n] = o2;
                o[((size_t)b*CH+c+3)*ND+n] = o3;
            } else {
                *(float4*)&o[((size_t)b*ND+n)*CH+c] = make_float4(o0,o1,o2,o3);
            }
        }
    } else {
        for (int c = 0; c < CH; c++) {
            float ov = w0*fa[c] + w1*fb[c] + w2*fc[c];
            if (TOUT) o[((size_t)b*CH+c)*ND+n] = ov;
            else      o[((size_t)b*ND+n)*CH+c] = ov;
        }
    }
}

// ---------------- SA1 grouping: kNN-16 + gather (two-phase, vector stores) ---
__global__ __launch_bounds__(128) void k_g1(const float* __restrict__ xyz,
                                            const float* __restrict__ fl,
                                            const int* __restrict__ fps,
                                            float* __restrict__ x0)
{
    __shared__ float4 sp[512];
    __shared__ float4 scp[128];
    __shared__ int sni[128*16];
    const int b = blockIdx.y, blk = blockIdx.x, t = threadIdx.x;
    for (int i = t; i < 512; i += 128) {
        float X = xyz[(b*3+0)*512+i], Y = xyz[(b*3+1)*512+i], Z = xyz[(b*3+2)*512+i];
        sp[i] = make_float4(X, Y, Z, X*X+Y*Y+Z*Z);
    }
    __syncthreads();
    {
        int s = blk*128 + t;
        int c = fps[b*512 + s];
        float4 cp = sp[c];
        scp[t] = cp;
        float nd[16]; int ni[16];
        #pragma unroll
        for (int k = 0; k < 16; k++) { nd[k] = 1e30f; ni[k] = 0; }
        for (int m = 0; m < 512; m++) {
            float4 P = sp[m];
            float d = cp.w + P.w - 2.0f*(cp.x*P.x + cp.y*P.y + cp.z*P.z);
            if (d < nd[15]) {
                float cd = d; int ci = m;
                #pragma unroll
                for (int k = 0; k < 16; k++)
                    if (cd < nd[k]) { float td=nd[k]; int ti=ni[k]; nd[k]=cd; ni[k]=ci; cd=td; ci=ti; }
            }
        }
        #pragma unroll
        for (int k = 0; k < 16; k++) sni[t*16 + k] = ni[k];
    }
    __syncthreads();
    for (int it = 0; it < 16; it++) {
        int pair = it*128 + t;
        int cL = pair >> 4, k = pair & 15;
        int ni = sni[pair];
        float4 cp = scp[cL];
        float4 P = sp[ni];
        const float* fp = &fl[((size_t)b*512 + ni)*3];
        float f0 = fp[0], f1v = fp[1], f2v = fp[2];
        float* o = &x0[((size_t)((b*512 + blk*128 + cL)*16) + k)*8];
        *(float4*)&o[0] = make_float4(P.x-cp.x, P.y-cp.y, P.z-cp.z, f0);
        *(float4*)&o[4] = make_float4(f1v, f2v, 0.f, 0.f);
    }
}

// ---------------- SA2 grouping (two-phase, vector stores, stride 68) ---------
__global__ __launch_bounds__(128) void k_g2(const float* __restrict__ xyz,
                                            const float* __restrict__ feat,
                                            const int* __restrict__ fps,
                                            float* __restrict__ x0)
{
    __shared__ float4 sp[1024];
    __shared__ float4 scp[128];
    __shared__ int sni[128*16];
    const int b = blockIdx.y, blk = blockIdx.x, t = threadIdx.x;
    for (int i = t; i < 1024; i += 128) {
        float X = xyz[(b*3+0)*1024+i], Y = xyz[(b*3+1)*1024+i], Z = xyz[(b*3+2)*1024+i];
        sp[i] = make_float4(X, Y, Z, X*X+Y*Y+Z*Z);
    }
    __syncthreads();
    {
        int s = blk*128 + t;
        int c = fps[b*1024 + s];
        float4 cp = sp[c];
        scp[t] = cp;
        float nd[16]; int ni[16];
        #pragma unroll
        for (int k = 0; k < 16; k++) { nd[k] = 1e30f; ni[k] = 0; }
        for (int m = 0; m < 1024; m++) {
            float4 P = sp[m];
            float d = cp.w + P.w - 2.0f*(cp.x*P.x + cp.y*P.y + cp.z*P.z);
            if (d < nd[15]) {
                float cd = d; int ci = m;
                #pragma unroll
                for (int k = 0; k < 16; k++)
                    if (cd < nd[k]) { float td=nd[k]; int ti=ni[k]; nd[k]=cd; ni[k]=ci; cd=td; ci=ti; }
            }
        }
        #pragma unroll
        for (int k = 0; k < 16; k++) sni[t*16 + k] = ni[k];
    }
    __syncthreads();
    for (int it = 0; it < 16; it++) {
        int pair = it*128 + t;
        int cL = pair >> 4, k = pair & 15;
        int ni = sni[pair];
        float4 cp = scp[cL];
        float4 P = sp[ni];
        const float4* fp = (const float4*)&feat[((size_t)b*1024 + ni)*64];
        float* o = &x0[((size_t)((b*1024 + blk*128 + cL)*16) + k)*68];
        float4 v = fp[0];
        *(float4*)&o[0] = make_float4(P.x-cp.x, P.y-cp.y, P.z-cp.z, v.x);
        float4 prev = v;
        #pragma unroll
        for (int j = 1; j < 16; j++) {
            v = fp[j];
            *(float4*)&o[j*4] = make_float4(prev.y, prev.z, prev.w, v.x);
            prev = v;
        }
        *(float4*)&o[64] = make_float4(prev.y, prev.z, prev.w, 0.f);
    }
}

// ------- 1x1 conv (+IN/relu on load) + stats; POOL: fused per-center max/min --
template <int CIN, int XS, int COUT, int ACT, int POOL>
__global__ __launch_bounds__(128) void k_conv(const float* __restrict__ x,
                                              const float* __restrict__ w,
                                              const float* __restrict__ ab,
                                              float* __restrict__ y,
                                              float* __restrict__ part,
                                              float* __restrict__ pmx,
                                              float* __restrict__ pmn,
                                              int M, int nblk)
{
    constexpr int NCG = COUT/16, RG = 128/NCG, RPT = (CIN >= 64) ? 2 : 4;
    constexpr int TR = RG*RPT, SPAD = (CIN & 1) ? CIN : CIN + 1;
    constexpr int RGC = 16/RPT;          // row-groups per center
    constexpr int RGW = 32/NCG;          // row-groups per warp
    constexpr bool XW = (RGC > RGW);     // center spans two warps
    __shared__ __align__(16) float sw[CIN*COUT];
    __shared__ float sx[TR*SPAD], sa[CIN], sbb[CIN];
    __shared__ float sred[4][2*COUT];
    __shared__ float spool[2][4][(POOL && XW) ? COUT : 1];
    const int t = threadIdx.x, blk = blockIdx.x, b = blockIdx.y;
    for (int i = t; i < CIN*COUT; i += 128) sw[i] = w[i];
    if (ACT)
        for (int i = t; i < CIN; i += 128) {
            sa[i]  = ab[(b*CIN+i)*2];
            sbb[i] = ab[(b*CIN+i)*2+1];
        }
    if (ACT) __syncthreads();
    const float* xs = x + ((size_t)b*M + (size_t)blk*TR)*XS;
    for (int i = t; i < TR*XS; i += 128) {
        int r = i / XS, c = i - r*XS;
        if (c < CIN) {
            float v = xs[i];
            if (ACT) { v = fmaf(v, sa[c], sbb[c]); v = fmaxf(v, 0.f); }
            sx[r*SPAD + c] = v;
        }
    }
    __syncthreads();
    const int rg = t / NCG, cg = t - rg*NCG;
    float acc[RPT][16];
    #pragma unroll
    for (int r = 0; r < RPT; r++)
        #pragma unroll
        for (int j = 0; j < 16; j++) acc[r][j] = 0.f;
    for (int k = 0; k < CIN; k++) {
        float xv[RPT];
        #pragma unroll
        for (int r = 0; r < RPT; r++) xv[r] = sx[(rg*RPT+r)*SPAD + k];
        const float4* wp = (const float4*)&sw[k*COUT + cg*16];
        float4 w0 = wp[0], w1 = wp[1], w2 = wp[2], w3 = wp[3];
        float wv[16] = {w0.x,w0.y,w0.z,w0.w, w1.x,w1.y,w1.z,w1.w,
                        w2.x,w2.y,w2.z,w2.w, w3.x,w3.y,w3.z,w3.w};
        #pragma unroll
        for (int r = 0; r < RPT; r++)
            #pragma unroll
            for (int j = 0; j < 16; j++) acc[r][j] = fmaf(xv[r], wv[j], acc[r][j]);
    }
    const int lane = t & 31, wp2 = t >> 5;
    float s1[16], s2[16];
    #pragma unroll
    for (int j = 0; j < 16; j++) { s1[j] = 0.f; s2[j] = 0.f; }
    if (!POOL) {
        float* yp = y + ((size_t)b*M + (size_t)blk*TR)*COUT;
        #pragma unroll
        for (int r = 0; r < RPT; r++) {
            int row = rg*RPT + r;
            #pragma unroll
            for (int j = 0; j < 16; j += 4)
                *(float4*)&yp[(size_t)row*COUT + cg*16 + j] =
                    make_float4(acc[r][j], acc[r][j+1], acc[r][j+2], acc[r][j+3]);
            #pragma unroll
            for (int j = 0; j < 16; j++) { s1[j] += acc[r][j]; s2[j] += acc[r][j]*acc[r][j]; }
        }
    } else {
        float mx[16], mn[16];
        #pragma unroll
        for (int j = 0; j < 16; j++) {
            mx[j] = acc[0][j]; mn[j] = acc[0][j];
            s1[j] = acc[0][j]; s2[j] = acc[0][j]*acc[0][j];
        }
        #pragma unroll
        for (int r = 1; r < RPT; r++)
            #pragma unroll
            for (int j = 0; j < 16; j++) {
                float v = acc[r][j];
                mx[j] = fmaxf(mx[j], v); mn[j] = fminf(mn[j], v);
                s1[j] += v; s2[j] += v*v;
            }
        constexpr int RED = (RGC < RGW) ? RGC : RGW;
        #pragma unroll
        for (int off = NCG; off < NCG*RED; off <<= 1)
            #pragma unroll
            for (int j = 0; j < 16; j++) {
                mx[j] = fmaxf(mx[j], __shfl_xor_sync(0xffffffffu, mx[j], off));
                mn[j] = fminf(mn[j], __shfl_xor_sync(0xffffffffu, mn[j], off));
            }
        const int S = M/16;
        if (!XW) {
            if ((rg % RGC) == 0) {
                int center = blk*(TR/16) + rg/RGC;
                float* px = pmx + ((size_t)b*S + center)*COUT + cg*16;
                float* pn = pmn + ((size_t)b*S + center)*COUT + cg*16;
                #pragma unroll
                for (int j = 0; j < 16; j += 4) {
                    *(float4*)&px[j] = make_float4(mx[j], mx[j+1], mx[j+2], mx[j+3]);
                    *(float4*)&pn[j] = make_float4(mn[j], mn[j+1], mn[j+2], mn[j+3]);
                }
            }
        } else {
            if (lane < NCG) {
                #pragma unroll
                for (int j = 0; j < 16; j++) {
                    spool[0][wp2][lane*16 + j] = mx[j];
                    spool[1][wp2][lane*16 + j] = mn[j];
                }
            }
        }
    }
    // stats cross-lane reduction (lanes sharing cg; NCG | 32)
    #pragma unroll
    for (int off = NCG; off < 32; off <<= 1) {
        #pragma unroll
        for (int j = 0; j < 16; j++) {
            s1[j] += __shfl_xor_sync(0xffffffffu, s1[j], off);
            s2[j] += __shfl_xor_sync(0xffffffffu, s2[j], off);
        }
    }
    if (lane < NCG) {
        #pragma unroll
        for (int j = 0; j < 16; j++) {
            sred[wp2][lane*16 + j]        = s1[j];
            sred[wp2][COUT + lane*16 + j] = s2[j];
        }
    }
    __syncthreads();
    if (t < COUT) {
        float a1 = sred[0][t] + sred[1][t] + sred[2][t] + sred[3][t];
        float a2 = sred[0][COUT+t] + sred[1][COUT+t] + sred[2][COUT+t] + sred[3][COUT+t];
        part[(((size_t)b*nblk + blk)*COUT + t)*2 + 0] = a1;
        part[(((size_t)b*nblk + blk)*COUT + t)*2 + 1] = a2;
    }
    if (POOL && XW) {
        const int S = M/16;
        if (t < COUT) {
            float mx0 = fmaxf(spool[0][0][t], spool[0][1][t]);
            float mn0 = fminf(spool[1][0][t], spool[1][1][t]);
            float mx1 = fmaxf(spool[0][2][t], spool[0][3][t]);
            float mn1 = fminf(spool[1][2][t], spool[1][3][t]);
            int c0 = blk*(TR/16);
            pmx[((size_t)b*S + c0  )*COUT + t] = mx0;
            pmn[((size_t)b*S + c0  )*COUT + t] = mn0;
            pmx[((size_t)b*S + c0+1)*COUT + t] = mx1;
            pmn[((size_t)b*S + c0+1)*COUT + t] = mn1;
        }
    }
}

// ---------------- IN stats finalize (warp per channel) ------------------------
template <int COUT>
__global__ __launch_bounds__(256) void k_fin(const float* __restrict__ part,
                                             const float* __restrict__ gamma,
                                             const float* __restrict__ beta,
                                             float* __restrict__ ab,
                                             int nblk, float invn)
{
    int b = blockIdx.x;
    int wp = threadIdx.x >> 5, lane = threadIdx.x & 31;
    int c = blockIdx.y*8 + wp;
    float s1 = 0.f, s2 = 0.f;
    for (int i = lane; i < nblk; i += 32) {
        const float* p = &part[(((size_t)b*nblk + i)*COUT + c)*2];
        s1 += p[0]; s2 += p[1];
    }
    #pragma unroll
    for (int o = 16; o; o >>= 1) {
        s1 += __shfl_down_sync(0xffffffffu, s1, o);
        s2 += __shfl_down_sync(0xffffffffu, s2, o);
    }
    if (lane == 0) {
        float mu = s1*invn;
        float var = s2*invn - mu*mu;
        float rs = 1.0f / sqrtf(var + 1e-5f);
        float A = gamma[c]*rs;
        ab[(b*COUT+c)*2 + 0] = A;
        ab[(b*COUT+c)*2 + 1] = beta[c] - mu*A;
    }
}

// ---------------- pooled finalize: relu(max(A*mx+B, A*mn+B)) ------------------
template <int COUT>
__global__ void k_pfin(const float* __restrict__ pmx, const float* __restrict__ pmn,
                       const float* __restrict__ ab, float* __restrict__ o)
{
    int s = blockIdx.x, b = blockIdx.y, c = threadIdx.x, S = gridDim.x;
    float A = ab[(b*COUT+c)*2], Bc = ab[(b*COUT+c)*2+1];
    size_t idx = ((size_t)b*S + s)*COUT + c;
    float v = fmaxf(fmaf(A, pmx[idx], Bc), fmaf(A, pmn[idx], Bc));
    o[idx] = fmaxf(v, 0.f);
}

// ---------------- launch -----------------------------------------------------
extern "C" void kernel_launch(void* const* d_in, const int* in_sizes, int n_in,
                              void* d_out, int out_size)
{
    const float* pc0 = (const float*)d_in[0];
    const float* pc1 = (const float*)d_in[1];
    const float* pc2 = (const float*)d_in[2];
    const float* pc3 = (const float*)d_in[3];
    const float* q3  = (const float*)d_in[4];
    const float* f1  = (const float*)d_in[5];
    const float* f2  = (const float*)d_in[6];
    const float* eps = (const float*)d_in[7];
    const float* w10 = (const float*)d_in[8];
    const float* w11 = (const float*)d_in[9];
    const float* w12 = (const float*)d_in[10];
    const float* g10 = (const float*)d_in[11]; const float* b10 = (const float*)d_in[12];
    const float* g11 = (const float*)d_in[13]; const float* b11 = (const float*)d_in[14];
    const float* g12 = (const float*)d_in[15]; const float* b12 = (const float*)d_in[16];
    const float* w20 = (const float*)d_in[17];
    const float* w21 = (const float*)d_in[18];
    const float* w22 = (const float*)d_in[19];
    const float* g20 = (const float*)d_in[20]; const float* b20 = (const float*)d_in[21];
    const float* g21 = (const float*)d_in[22]; const float* b21 = (const float*)d_in[23];
    const float* g22 = (const float*)d_in[24]; const float* b22 = (const float*)d_in[25];
    float* out = (float*)d_out;

    void *flow0, *flow0us, *in1, *in2, *fps1, *fps2, *x0a, *ya, *yb, *yc;
    void *cf2, *cf1, *x0b, *za, *zb, *zc, *cf1o, *part, *ab;
    cudaGetSymbolAddress(&flow0, g_flow0);
    cudaGetSymbolAddress(&flow0us, g_flow0us);
    cudaGetSymbolAddress(&in1, g_in1);
    cudaGetSymbolAddress(&in2, g_in2);
    cudaGetSymbolAddress(&fps1, g_fps1);
    cudaGetSymbolAddress(&fps2, g_fps2);
    cudaGetSymbolAddress(&x0a, g_x0a);
    cudaGetSymbolAddress(&ya, g_ya);
    cudaGetSymbolAddress(&yb, g_yb);
    cudaGetSymbolAddress(&yc, g_yc);
    cudaGetSymbolAddress(&cf2, g_cf2);
    cudaGetSymbolAddress(&cf1, g_cf1);
    cudaGetSymbolAddress(&x0b, g_x0b);
    cudaGetSymbolAddress(&za, g_za);
    cudaGetSymbolAddress(&zb, g_zb);
    cudaGetSymbolAddress(&zc, g_zc);
    cudaGetSymbolAddress(&cf1o, g_cf1o);
    cudaGetSymbolAddress(&part, g_part);
    cudaGetSymbolAddress(&ab, g_ab);

    float* pmx1 = (float*)yc;
    float* pmn1 = (float*)yc + 8*512*64;
    float* pmx2 = (float*)zc;
    float* pmn2 = (float*)zc + (size_t)8*1024*128;

    // ONE side stream (R5-verified topology — passes the teardown memory check)
    cudaStream_t s2;
    cudaStreamCreateWithFlags(&s2, cudaStreamNonBlocking);
    cudaEvent_t eF, e1, e2;
    cudaEventCreateWithFlags(&eF, cudaEventDisableTiming);
    cudaEventCreateWithFlags(&e1, cudaEventDisableTiming);
    cudaEventCreateWithFlags(&e2, cudaEventDisableTiming);

    cudaEventRecord(eF, 0);
    cudaStreamWaitEvent(s2, eF, 0);
    k_fpsA<<<8, 256, 0, s2>>>(pc2, (int*)fps1);                                   // [0]
    cudaEventRecord(e1, s2);
    k_fpsB<<<8, 256, 0, s2>>>(pc1, (int*)fps2);                                   // [1]
    cudaEventRecord(e2, s2);
    k_inorm<<<dim3(8,2), 256>>>(f1, f2, (float*)in1, (float*)in2);                // [2]
    k_corr<<<dim3(4,8), 256>>>(f1, f2, (float*)in1, (float*)in2, pc3, q3, eps, (float*)flow0); // [3] probe
    k_prop<256,3,false><<<dim3(4,8), 128>>>(pc2, pc3, (float*)flow0, (float*)flow0us, 512);

    cudaStreamWaitEvent(0, e1, 0);
    k_g1<<<dim3(4,8), 128>>>(pc2, (float*)flow0us, (int*)fps1, (float*)x0a);

    k_conv<6,8,32,0,0><<<dim3(32,8), 128>>>((float*)x0a, w10, (float*)ab, (float*)ya, (float*)part, nullptr, nullptr, 8192, 32);
    k_fin<32><<<dim3(8,4), 256>>>((float*)part, g10, b10, (float*)ab, 32, 1.0f/8192.0f);
    k_conv<32,32,32,1,0><<<dim3(32,8), 128>>>((float*)ya, w11, (float*)ab, (float*)yb, (float*)part, nullptr, nullptr, 8192, 32);
    k_fin<32><<<dim3(8,4), 256>>>((float*)part, g11, b11, (float*)ab, 32, 1.0f/8192.0f);
    k_conv<32,32,64,1,1><<<dim3(64,8), 128>>>((float*)yb, w12, (float*)ab, nullptr, (float*)part, pmx1, pmn1, 8192, 64);
    k_fin<64><<<dim3(8,8), 256>>>((float*)part, g12, b12, (float*)ab, 64, 1.0f/8192.0f);
    k_pfin<64><<<dim3(512,8), 64>>>(pmx1, pmn1, (float*)ab, (float*)cf2);

    k_prop<512,64,false><<<dim3(8,8), 128>>>(pc1, pc2, (float*)cf2, (float*)cf1, 1024);
    cudaStreamWaitEvent(0, e2, 0);
    k_g2<<<dim3(8,8), 128>>>(pc1, (float*)cf1, (int*)fps2, (float*)x0b);

    k_conv<67,68,64,0,0><<<dim3(256,8), 128>>>((float*)x0b, w20, (float*)ab, (float*)za, (float*)part, nullptr, nullptr, 16384, 256);
    k_fin<64><<<dim3(8,8), 256>>>((float*)part, g20, b20, (float*)ab, 256, 1.0f/16384.0f);
    k_conv<64,64,64,1,0><<<dim3(256,8), 128>>>((float*)za, w21, (float*)ab, (float*)zb, (float*)part, nullptr, nullptr, 16384, 256);
    k_fin<64><<<dim3(8,8), 256>>>((float*)part, g21, b21, (float*)ab, 256, 1.0f/16384.0f);
    k_conv<64,64,128,1,1><<<dim3(512,8), 128>>>((float*)zb, w22, (float*)ab, nullptr, (float*)part, pmx2, pmn2, 16384, 512);
    k_fin<128><<<dim3(8,16), 256>>>((float*)part, g22, b22, (float*)ab, 512, 1.0f/16384.0f);
    k_pfin<128><<<dim3(1024,8), 128>>>(pmx2, pmn2, (float*)ab, (float*)cf1o);

    k_prop<1024,128,true><<<dim3(64,8), 128>>>(pc0, pc1, (float*)cf1o, out, 8192);
}

// round 12
// speedup vs baseline: 2.0095x; 1.0048x over previous
#include <cuda_runtime.h>
#include <math.h>

// ---------------- scratch ----------------
__device__ float g_flow0 [8*256*3];
__device__ float g_flow0us[8*512*3];
__device__ float g_in1   [8*256];
__device__ float g_in2   [8*256];
__device__ int   g_fps1  [8*512];
__device__ int   g_fps2  [8*1024];
__device__ float g_x0a   [8*512*16*8];
__device__ float g_ya    [8*8192*32];
__device__ float g_yb    [8*8192*32];
__device__ float g_yc    [8*8192*64];     // reused: SA1 pooled max/min
__device__ float g_cf2   [8*512*64];
__device__ float g_cf1   [8*1024*64];
__device__ float g_x0b   [(size_t)8*1024*16*68];
__device__ float g_za    [(size_t)8*16384*64];
__device__ float g_zb    [(size_t)8*16384*64];
__device__ float g_zc    [(size_t)8*16384*128]; // reused: SA2 pooled max/min
__device__ float g_cf1o  [8*1024*128];
__device__ float g_part  [(size_t)8*512*128*2];
__device__ float g_ab    [8*128*2];

// ---------------- FPS (REDUX-based, 1 barrier/iter) ---------------------------
template <int N, int NP>
__device__ __forceinline__ void fps_run(const float* __restrict__ src, int b,
                                        int* __restrict__ out,
                                        float4* sp, unsigned long long (*skey)[8])
{
    int t = threadIdx.x;
    float px[NP], py[NP], pz[NP], md[NP];
    #pragma unroll
    for (int j = 0; j < NP; j++) {
        int p = t*NP + j;
        px[j] = src[(b*3+0)*N + p];
        py[j] = src[(b*3+1)*N + p];
        pz[j] = src[(b*3+2)*N + p];
        sp[p] = make_float4(px[j], py[j], pz[j], 0.f);
        md[j] = 1e10f;
    }
    __syncthreads();
    int far = 0;
    for (int it = 0; it < N; it++) {
        if (t == 0) out[it] = far;
        float4 F = sp[far];
        unsigned long long best = 0ull;
        #pragma unroll
        for (int j = 0; j < NP; j++) {
            float dx = px[j]-F.x, dy = py[j]-F.y, dz = pz[j]-F.z;
            float d = dx*dx + dy*dy + dz*dz;
            md[j] = fminf(md[j], d);
            unsigned long long key =
                ((unsigned long long)__float_as_uint(md[j]) << 32) |
                (unsigned)(~(t*NP + j));
            best = (key > best) ? key : best;
        }
        unsigned dbits = (unsigned)(best >> 32);
        unsigned m   = __reduce_max_sync(0xffffffffu, dbits);
        unsigned cand = (dbits == m) ? (unsigned)best : 0u;
        unsigned nim  = __reduce_max_sync(0xffffffffu, cand);
        if ((t & 31) == 0) skey[it & 1][t >> 5] = ((unsigned long long)m << 32) | nim;
        __syncthreads();
        unsigned long long bk = skey[it & 1][0];
        #pragma unroll
        for (int q = 1; q < 8; q++) {
            unsigned long long kq = skey[it & 1][q];
            bk = (kq > bk) ? kq : bk;
        }
        far = (int)(~(unsigned)bk);
    }
}

__global__ __launch_bounds__(256) void k_fpsA(const float* __restrict__ pc,
                                              int* __restrict__ o1)
{
    __shared__ float4 sp[512];
    __shared__ unsigned long long skey[2][8];
    fps_run<512, 2>(pc, blockIdx.x, o1 + blockIdx.x*512, sp, skey);
}

__global__ __launch_bounds__(256) void k_fpsB(const float* __restrict__ pc,
                                              int* __restrict__ o2)
{
    __shared__ float4 sp[1024];
    __shared__ unsigned long long skey[2][8];
    fps_run<1024, 4>(pc, blockIdx.x, o2 + blockIdx.x*1024, sp, skey);
}

// ---------------- feature inverse norms --------------------------------------
__global__ void k_inorm(const float* __restrict__ f1, const float* __restrict__ f2,
                        float* __restrict__ o1, float* __restrict__ o2)
{
    int b = blockIdx.x, which = blockIdx.y, n = threadIdx.x;
    const float* f = which ? f2 : f1;
    float* o = which ? o2 : o1;
    float s = 0.f;
    for (int c = 0; c < 256; c++) { float v = f[(b*256+c)*256 + n]; s += v*v; }
    o[b*256+n] = 1.0f / sqrtf(s + 1e-8f);
}

// ---------------- global correlation -> flow0 (32-row tiles, 64 blocks) -------
__global__ __launch_bounds__(256) void k_corr(const float* __restrict__ f1,
                                              const float* __restrict__ f2,
                                              const float* __restrict__ in1,
                                              const float* __restrict__ in2,
                                              const float* __restrict__ p1g,
                                              const float* __restrict__ p2g,
                                              const float* __restrict__ epsin,
                                              float* __restrict__ flow0)
{
    __shared__ float sA[32*32], sB[32*256];
    __shared__ float si1[32], si2[256], sq1[32], sq2[256];
    __shared__ float sp1[32*3], sp2[256*3];
    const int b = blockIdx.y, n0 = blockIdx.x*32, tid = threadIdx.x;
    for (int i = tid; i < 32; i += 256) {
        si1[i] = in1[b*256 + n0 + i];
        float X = p1g[(b*3+0)*256+n0+i], Y = p1g[(b*3+1)*256+n0+i], Z = p1g[(b*3+2)*256+n0+i];
        sp1[i*3] = X; sp1[i*3+1] = Y; sp1[i*3+2] = Z; sq1[i] = X*X+Y*Y+Z*Z;
    }
    for (int i = tid; i < 256; i += 256) {
        si2[i] = in2[b*256+i];
        float X = p2g[(b*3+0)*256+i], Y = p2g[(b*3+1)*256+i], Z = p2g[(b*3+2)*256+i];
        sp2[i*3] = X; sp2[i*3+1] = Y; sp2[i*3+2] = Z; sq2[i] = X*X+Y*Y+Z*Z;
    }
    const float inv_eps = 1.0f / (expf(epsin[0]) + 0.03f);
    const int ty = tid >> 5, tx = tid & 31;
    float acc[4][8];
    #pragma unroll
    for (int i = 0; i < 4; i++)
        #pragma unroll
        for (int j = 0; j < 8; j++) acc[i][j] = 0.f;
    for (int cc = 0; cc < 256; cc += 32) {
        __syncthreads();
        for (int i = tid; i < 1024; i += 256) {
            int c = i >> 5, n = i & 31;
            sA[i] = f1[(b*256 + cc + c)*256 + n0 + n];
        }
        for (int i = tid; i < 8192; i += 256) {
            int c = i >> 8, m = i & 255;
            sB[i] = f2[(b*256 + cc + c)*256 + m];
        }
        __syncthreads();
        #pragma unroll 4
        for (int c = 0; c < 32; c++) {
            float a[4], bv[8];
            #pragma unroll
            for (int i = 0; i < 4; i++) a[i] = sA[c*32 + ty*4 + i];
            #pragma unroll
            for (int j = 0; j < 8; j++) bv[j] = sB[c*256 + tx + 32*j];
            #pragma unroll
            for (int i = 0; i < 4; i++)
                #pragma unroll
                for (int j = 0; j < 8; j++) acc[i][j] = fmaf(a[i], bv[j], acc[i][j]);
        }
    }
    #pragma unroll
    for (int i = 0; i < 4; i++) {
        int n = ty*4 + i;
        float i1v = si1[n], q1 = sq1[n];
        float px = sp1[n*3], py = sp1[n*3+1], pz = sp1[n*3+2];
        float s0 = 0.f, s1 = 0.f, s2 = 0.f, s3 = 0.f;
        #pragma unroll
        for (int j = 0; j < 8; j++) {
            int m = tx + 32*j;
            float Cv = 1.0f - acc[i][j]*i1v*si2[m];
            float qx = sp2[m*3], qy = sp2[m*3+1], qz = sp2[m*3+2];
            float dm = q1 + sq2[m] - 2.0f*(px*qx + py*qy + pz*qz);
            float cv = (dm < 100.0f) ? expf(-Cv*inv_eps) : 0.0f;
            s0 += cv; s1 += cv*qx; s2 += cv*qy; s3 += cv*qz;
        }
        #pragma unroll
        for (int o = 16; o; o >>= 1) {
            s0 += __shfl_down_sync(0xffffffffu, s0, o);
            s1 += __shfl_down_sync(0xffffffffu, s1, o);
            s2 += __shfl_down_sync(0xffffffffu, s2, o);
            s3 += __shfl_down_sync(0xffffffffu, s3, o);
        }
        if (tx == 0) {
            float inv = 1.0f / (s0 + 1e-8f);
            int gn = n0 + n;
            flow0[(b*256+gn)*3+0] = s1*inv - px;
            flow0[(b*256+gn)*3+1] = s2*inv - py;
            flow0[(b*256+gn)*3+2] = s3*inv - pz;
        }
    }
}

// ---------------- feature propagation (exact branchless 3-NN) -----------------
template <int NS, int CH, bool TOUT>
__global__ __launch_bounds__(128) void k_prop(const float* __restrict__ x1,
                                              const float* __restrict__ x2,
                                              const float* __restrict__ f,
                                              float* __restrict__ o, int ND)
{
    __shared__ float4 sp[NS];
    const int b = blockIdx.y, t = threadIdx.x;
    for (int i = t; i < NS; i += 128) {
        float X = x2[(b*3+0)*NS+i], Y = x2[(b*3+1)*NS+i], Z = x2[(b*3+2)*NS+i];
        sp[i] = make_float4(X, Y, Z, X*X+Y*Y+Z*Z);
    }
    __syncthreads();
    int n = blockIdx.x*128 + t;
    float x = x1[(b*3+0)*ND+n], y = x1[(b*3+1)*ND+n], z = x1[(b*3+2)*ND+n];
    float q = x*x + y*y + z*z;
    float d0 = 1e30f, d1 = 1e30f, d2 = 1e30f;
    int i0 = 0, i1 = 0, i2 = 0;
    #pragma unroll 4
    for (int m = 0; m < NS; m++) {
        float4 P = sp[m];
        float d = q + P.w - 2.0f*(x*P.x + y*P.y + z*P.z);
        bool b0 = d < d0, b1 = d < d1, b2 = d < d2;
        d2 = b1 ? d1 : (b2 ? d : d2);
        i2 = b1 ? i1 : (b2 ? m : i2);
        d1 = b0 ? d0 : (b1 ? d : d1);
        i1 = b0 ? i0 : (b1 ? m : i1);
        d0 = b0 ? d : d0;
        i0 = b0 ? m : i0;
    }
    float w0 = 1.0f/(d0+1e-8f), w1 = 1.0f/(d1+1e-8f), w2 = 1.0f/(d2+1e-8f);
    float ws = 1.0f/(w0+w1+w2); w0 *= ws; w1 *= ws; w2 *= ws;
    const float* fa = &f[((size_t)b*NS+i0)*CH];
    const float* fb = &f[((size_t)b*NS+i1)*CH];
    const float* fc = &f[((size_t)b*NS+i2)*CH];
    if (CH % 4 == 0) {
        for (int c = 0; c < CH; c += 4) {
            float4 A = *(const float4*)&fa[c];
            float4 Bq = *(const float4*)&fb[c];
            float4 Cq = *(const float4*)&fc[c];
            float o0 = w0*A.x + w1*Bq.x + w2*Cq.x;
            float o1 = w0*A.y + w1*Bq.y + w2*Cq.y;
            float o2 = w0*A.z + w1*Bq.z + w2*Cq.z;
            float o3 = w0*A.w + w1*Bq.w + w2*Cq.w;
            if (TOUT) {
                o[((size_t)b*CH+c+0)*ND+n] = o0;
                o[((size_t)b*CH+c+1)*ND+n] = o1;
                o[((size_t)b*CH+c+2)*ND+n] = o2;
                o[((size_t)b*CH+c+3)*ND+n] = o3;
            } else {
                *(float4*)&o[((size_t)b*ND+n)*CH+c] = make_float4(o0,o1,o2,o3);
            }
        }
    } else {
        for (int c = 0; c < CH; c++) {
            float ov = w0*fa[c] + w1*fb[c] + w2*fc[c];
            if (TOUT) o[((size_t)b*CH+c)*ND+n] = ov;
            else      o[((size_t)b*ND+n)*CH+c] = ov;
        }
    }
}

// ---------------- SA1 grouping: kNN-16 + gather (two-phase, vector stores) ---
__global__ __launch_bounds__(128) void k_g1(const float* __restrict__ xyz,
                                            const float* __restrict__ fl,
                                            const int* __restrict__ fps,
                                            float* __restrict__ x0)
{
    __shared__ float4 sp[512];
    __shared__ float4 scp[128];
    __shared__ int sni[128*16];
    const int b = blockIdx.y, blk = blockIdx.x, t = threadIdx.x;
    for (int i = t; i < 512; i += 128) {
        float X = xyz[(b*3+0)*512+i], Y = xyz[(b*3+1)*512+i], Z = xyz[(b*3+2)*512+i];
        sp[i] = make_float4(X, Y, Z, X*X+Y*Y+Z*Z);
    }
    __syncthreads();
    {
        int s = blk*128 + t;
        int c = fps[b*512 + s];
        float4 cp = sp[c];
        scp[t] = cp;
        float nd[16]; int ni[16];
        #pragma unroll
        for (int k = 0; k < 16; k++) { nd[k] = 1e30f; ni[k] = 0; }
        for (int m = 0; m < 512; m++) {
            float4 P = sp[m];
            float d = cp.w + P.w - 2.0f*(cp.x*P.x + cp.y*P.y + cp.z*P.z);
            if (d < nd[15]) {
                float cd = d; int ci = m;
                #pragma unroll
                for (int k = 0; k < 16; k++)
                    if (cd < nd[k]) { float td=nd[k]; int ti=ni[k]; nd[k]=cd; ni[k]=ci; cd=td; ci=ti; }
            }
        }
        #pragma unroll
        for (int k = 0; k < 16; k++) sni[t*16 + k] = ni[k];
    }
    __syncthreads();
    for (int it = 0; it < 16; it++) {
        int pair = it*128 + t;
        int cL = pair >> 4, k = pair & 15;
        int ni = sni[pair];
        float4 cp = scp[cL];
        float4 P = sp[ni];
        const float* fp = &fl[((size_t)b*512 + ni)*3];
        float f0 = fp[0], f1v = fp[1], f2v = fp[2];
        float* o = &x0[((size_t)((b*512 + blk*128 + cL)*16) + k)*8];
        *(float4*)&o[0] = make_float4(P.x-cp.x, P.y-cp.y, P.z-cp.z, f0);
        *(float4*)&o[4] = make_float4(f1v, f2v, 0.f, 0.f);
    }
}

// ---------------- SA2 grouping (two-phase, vector stores, stride 68) ---------
__global__ __launch_bounds__(128) void k_g2(const float* __restrict__ xyz,
                                            const float* __restrict__ feat,
                                            const int* __restrict__ fps,
                                            float* __restrict__ x0)
{
    __shared__ float4 sp[1024];
    __shared__ float4 scp[128];
    __shared__ int sni[128*16];
    const int b = blockIdx.y, blk = blockIdx.x, t = threadIdx.x;
    for (int i = t; i < 1024; i += 128) {
        float X = xyz[(b*3+0)*1024+i], Y = xyz[(b*3+1)*1024+i], Z = xyz[(b*3+2)*1024+i];
        sp[i] = make_float4(X, Y, Z, X*X+Y*Y+Z*Z);
    }
    __syncthreads();
    {
        int s = blk*128 + t;
        int c = fps[b*1024 + s];
        float4 cp = sp[c];
        scp[t] = cp;
        float nd[16]; int ni[16];
        #pragma unroll
        for (int k = 0; k < 16; k++) { nd[k] = 1e30f; ni[k] = 0; }
        for (int m = 0; m < 1024; m++) {
            float4 P = sp[m];
            float d = cp.w + P.w - 2.0f*(cp.x*P.x + cp.y*P.y + cp.z*P.z);
            if (d < nd[15]) {
                float cd = d; int ci = m;
                #pragma unroll
                for (int k = 0; k < 16; k++)
                    if (cd < nd[k]) { float td=nd[k]; int ti=ni[k]; nd[k]=cd; ni[k]=ci; cd=td; ci=ti; }
            }
        }
        #pragma unroll
        for (int k = 0; k < 16; k++) sni[t*16 + k] = ni[k];
    }
    __syncthreads();
    for (int it = 0; it < 16; it++) {
        int pair = it*128 + t;
        int cL = pair >> 4, k = pair & 15;
        int ni = sni[pair];
        float4 cp = scp[cL];
        float4 P = sp[ni];
        const float4* fp = (const float4*)&feat[((size_t)b*1024 + ni)*64];
        float* o = &x0[((size_t)((b*1024 + blk*128 + cL)*16) + k)*68];
        float4 v = fp[0];
        *(float4*)&o[0] = make_float4(P.x-cp.x, P.y-cp.y, P.z-cp.z, v.x);
        float4 prev = v;
        #pragma unroll
        for (int j = 1; j < 16; j++) {
            v = fp[j];
            *(float4*)&o[j*4] = make_float4(prev.y, prev.z, prev.w, v.x);
            prev = v;
        }
        *(float4*)&o[64] = make_float4(prev.y, prev.z, prev.w, 0.f);
    }
}

// ------- 1x1 conv (+IN/relu on load) + stats; POOL: fused per-center max/min --
// Vectorized: float4 weight/input staging, K unrolled by 4 with LDS.128 x-loads.
template <int CIN, int XS, int COUT, int ACT, int POOL>
__global__ __launch_bounds__(128) void k_conv(const float* __restrict__ x,
                                              const float* __restrict__ w,
                                              const float* __restrict__ ab,
                                              float* __restrict__ y,
                                              float* __restrict__ part,
                                              float* __restrict__ pmx,
                                              float* __restrict__ pmn,
                                              int M, int nblk)
{
    constexpr int NCG = COUT/16, RG = 128/NCG, RPT = (CIN >= 64) ? 2 : 4;
    constexpr int TR = RG*RPT;
    constexpr int SPAD4 = ((CIN % 8) == 0) ? CIN + 4 : ((CIN + 3) & ~3);
    constexpr int K4 = CIN & ~3;
    constexpr int RGC = 16/RPT;          // row-groups per center
    constexpr int RGW = 32/NCG;          // row-groups per warp
    constexpr bool XW = (RGC > RGW);     // center spans two warps
    __shared__ __align__(16) float sw[CIN*COUT];
    __shared__ __align__(16) float sx[TR*SPAD4];
    __shared__ float sa[CIN], sbb[CIN];
    __shared__ float sred[4][2*COUT];
    __shared__ float spool[2][4][(POOL && XW) ? COUT : 1];
    const int t = threadIdx.x, blk = blockIdx.x, b = blockIdx.y;
    for (int i4 = t; i4 < (CIN*COUT)/4; i4 += 128)
        ((float4*)sw)[i4] = ((const float4*)w)[i4];
    if (ACT)
        for (int i = t; i < CIN; i += 128) {
            sa[i]  = ab[(b*CIN+i)*2];
            sbb[i] = ab[(b*CIN+i)*2+1];
        }
    if (ACT) __syncthreads();
    const float* xs = x + ((size_t)b*M + (size_t)blk*TR)*XS;
    for (int i4 = t; i4 < TR*(XS/4); i4 += 128) {
        int r = i4 / (XS/4), c4 = i4 - r*(XS/4);
        float4 v = ((const float4*)xs)[i4];
        if (ACT) {
            int c = c4*4;
            v.x = fmaxf(fmaf(v.x, sa[c+0], sbb[c+0]), 0.f);
            v.y = fmaxf(fmaf(v.y, sa[c+1], sbb[c+1]), 0.f);
            v.z = fmaxf(fmaf(v.z, sa[c+2], sbb[c+2]), 0.f);
            v.w = fmaxf(fmaf(v.w, sa[c+3], sbb[c+3]), 0.f);
        }
        *(float4*)&sx[r*SPAD4 + c4*4] = v;
    }
    __syncthreads();
    const int rg = t / NCG, cg = t - rg*NCG;
    float acc[RPT][16];
    #pragma unroll
    for (int r = 0; r < RPT; r++)
        #pragma unroll
        for (int j = 0; j < 16; j++) acc[r][j] = 0.f;
    for (int k = 0; k < K4; k += 4) {
        float4 xv4[RPT];
        #pragma unroll
        for (int r = 0; r < RPT; r++)
            xv4[r] = *(const float4*)&sx[(rg*RPT+r)*SPAD4 + k];
        #pragma unroll
        for (int q = 0; q < 4; q++) {
            const float4* wp = (const float4*)&sw[(k+q)*COUT + cg*16];
            float4 w0 = wp[0], w1 = wp[1], w2 = wp[2], w3 = wp[3];
            float wv[16] = {w0.x,w0.y,w0.z,w0.w, w1.x,w1.y,w1.z,w1.w,
                            w2.x,w2.y,w2.z,w2.w, w3.x,w3.y,w3.z,w3.w};
            #pragma unroll
            for (int r = 0; r < RPT; r++) {
                float xq = (q==0) ? xv4[r].x : (q==1) ? xv4[r].y : (q==2) ? xv4[r].z : xv4[r].w;
                #pragma unroll
                for (int j = 0; j < 16; j++) acc[r][j] = fmaf(xq, wv[j], acc[r][j]);
            }
        }
    }
    for (int k = K4; k < CIN; k++) {
        float xv[RPT];
        #pragma unroll
        for (int r = 0; r < RPT; r++) xv[r] = sx[(rg*RPT+r)*SPAD4 + k];
        const float4* wp = (const float4*)&sw[k*COUT + cg*16];
        float4 w0 = wp[0], w1 = wp[1], w2 = wp[2], w3 = wp[3];
        float wv[16] = {w0.x,w0.y,w0.z,w0.w, w1.x,w1.y,w1.z,w1.w,
                        w2.x,w2.y,w2.z,w2.w, w3.x,w3.y,w3.z,w3.w};
        #pragma unroll
        for (int r = 0; r < RPT; r++)
            #pragma unroll
            for (int j = 0; j < 16; j++) acc[r][j] = fmaf(xv[r], wv[j], acc[r][j]);
    }
    const int lane = t & 31, wp2 = t >> 5;
    float s1[16], s2[16];
    #pragma unroll
    for (int j = 0; j < 16; j++) { s1[j] = 0.f; s2[j] = 0.f; }
    if (!POOL) {
        float* yp = y + ((size_t)b*M + (size_t)blk*TR)*COUT;
        #pragma unroll
        for (int r = 0; r < RPT; r++) {
            int row = rg*RPT + r;
            #pragma unroll
            for (int j = 0; j < 16; j += 4)
                *(float4*)&yp[(size_t)row*COUT + cg*16 + j] =
                    make_float4(acc[r][j], acc[r][j+1], acc[r][j+2], acc[r][j+3]);
            #pragma unroll
            for (int j = 0; j < 16; j++) { s1[j] += acc[r][j]; s2[j] += acc[r][j]*acc[r][j]; }
        }
    } else {
        float mx[16], mn[16];
        #pragma unroll
        for (int j = 0; j < 16; j++) {
            mx[j] = acc[0][j]; mn[j] = acc[0][j];
            s1[j] = acc[0][j]; s2[j] = acc[0][j]*acc[0][j];
        }
        #pragma unroll
        for (int r = 1; r < RPT; r++)
            #pragma unroll
            for (int j = 0; j < 16; j++) {
                float v = acc[r][j];
                mx[j] = fmaxf(mx[j], v); mn[j] = fminf(mn[j], v);
                s1[j] += v; s2[j] += v*v;
            }
        constexpr int RED = (RGC < RGW) ? RGC : RGW;
        #pragma unroll
        for (int off = NCG; off < NCG*RED; off <<= 1)
            #pragma unroll
            for (int j = 0; j < 16; j++) {
                mx[j] = fmaxf(mx[j], __shfl_xor_sync(0xffffffffu, mx[j], off));
                mn[j] = fminf(mn[j], __shfl_xor_sync(0xffffffffu, mn[j], off));
            }
        const int S = M/16;
        if (!XW) {
            if ((rg % RGC) == 0) {
                int center = blk*(TR/16) + rg/RGC;
                float* px = pmx + ((size_t)b*S + center)*COUT + cg*16;
                float* pn = pmn + ((size_t)b*S + center)*COUT + cg*16;
                #pragma unroll
                for (int j = 0; j < 16; j += 4) {
                    *(float4*)&px[j] = make_float4(mx[j], mx[j+1], mx[j+2], mx[j+3]);
                    *(float4*)&pn[j] = make_float4(mn[j], mn[j+1], mn[j+2], mn[j+3]);
                }
            }
        } else {
            if (lane < NCG) {
                #pragma unroll
                for (int j = 0; j < 16; j++) {
                    spool[0][wp2][lane*16 + j] = mx[j];
                    spool[1][wp2][lane*16 + j] = mn[j];
                }
            }
        }
    }
    // stats cross-lane reduction (lanes sharing cg; NCG | 32)
    #pragma unroll
    for (int off = NCG; off < 32; off <<= 1) {
        #pragma unroll
        for (int j = 0; j < 16; j++) {
            s1[j] += __shfl_xor_sync(0xffffffffu, s1[j], off);
            s2[j] += __shfl_xor_sync(0xffffffffu, s2[j], off);
        }
    }
    if (lane < NCG) {
        #pragma unroll
        for (int j = 0; j < 16; j++) {
            sred[wp2][lane*16 + j]        = s1[j];
            sred[wp2][COUT + lane*16 + j] = s2[j];
        }
    }
    __syncthreads();
    if (t < COUT) {
        float a1 = sred[0][t] + sred[1][t] + sred[2][t] + sred[3][t];
        float a2 = sred[0][COUT+t] + sred[1][COUT+t] + sred[2][COUT+t] + sred[3][COUT+t];
        part[(((size_t)b*nblk + blk)*COUT + t)*2 + 0] = a1;
        part[(((size_t)b*nblk + blk)*COUT + t)*2 + 1] = a2;
    }
    if (POOL && XW) {
        const int S = M/16;
        if (t < COUT) {
            float mx0 = fmaxf(spool[0][0][t], spool[0][1][t]);
            float mn0 = fminf(spool[1][0][t], spool[1][1][t]);
            float mx1 = fmaxf(spool[0][2][t], spool[0][3][t]);
            float mn1 = fminf(spool[1][2][t], spool[1][3][t]);
            int c0 = blk*(TR/16);
            pmx[((size_t)b*S + c0  )*COUT + t] = mx0;
            pmn[((size_t)b*S + c0  )*COUT + t] = mn0;
            pmx[((size_t)b*S + c0+1)*COUT + t] = mx1;
            pmn[((size_t)b*S + c0+1)*COUT + t] = mn1;
        }
    }
}

// ---------------- IN stats finalize (warp per channel) ------------------------
template <int COUT>
__global__ __launch_bounds__(256) void k_fin(const float* __restrict__ part,
                                             const float* __restrict__ gamma,
                                             const float* __restrict__ beta,
                                             float* __restrict__ ab,
                                             int nblk, float invn)
{
    int b = blockIdx.x;
    int wp = threadIdx.x >> 5, lane = threadIdx.x & 31;
    int c = blockIdx.y*8 + wp;
    float s1 = 0.f, s2 = 0.f;
    for (int i = lane; i < nblk; i += 32) {
        const float* p = &part[(((size_t)b*nblk + i)*COUT + c)*2];
        s1 += p[0]; s2 += p[1];
    }
    #pragma unroll
    for (int o = 16; o; o >>= 1) {
        s1 += __shfl_down_sync(0xffffffffu, s1, o);
        s2 += __shfl_down_sync(0xffffffffu, s2, o);
    }
    if (lane == 0) {
        float mu = s1*invn;
        float var = s2*invn - mu*mu;
        float rs = 1.0f / sqrtf(var + 1e-5f);
        float A = gamma[c]*rs;
        ab[(b*COUT+c)*2 + 0] = A;
        ab[(b*COUT+c)*2 + 1] = beta[c] - mu*A;
    }
}

// ---------------- pooled finalize: relu(max(A*mx+B, A*mn+B)) ------------------
template <int COUT>
__global__ void k_pfin(const float* __restrict__ pmx, const float* __restrict__ pmn,
                       const float* __restrict__ ab, float* __restrict__ o)
{
    int s = blockIdx.x, b = blockIdx.y, c = threadIdx.x, S = gridDim.x;
    float A = ab[(b*COUT+c)*2], Bc = ab[(b*COUT+c)*2+1];
    size_t idx = ((size_t)b*S + s)*COUT + c;
    float v = fmaxf(fmaf(A, pmx[idx], Bc), fmaf(A, pmn[idx], Bc));
    o[idx] = fmaxf(v, 0.f);
}

// ---------------- launch -----------------------------------------------------
extern "C" void kernel_launch(void* const* d_in, const int* in_sizes, int n_in,
                              void* d_out, int out_size)
{
    const float* pc0 = (const float*)d_in[0];
    const float* pc1 = (const float*)d_in[1];
    const float* pc2 = (const float*)d_in[2];
    const float* pc3 = (const float*)d_in[3];
    const float* q3  = (const float*)d_in[4];
    const float* f1  = (const float*)d_in[5];
    const float* f2  = (const float*)d_in[6];
    const float* eps = (const float*)d_in[7];
    const float* w10 = (const float*)d_in[8];
    const float* w11 = (const float*)d_in[9];
    const float* w12 = (const float*)d_in[10];
    const float* g10 = (const float*)d_in[11]; const float* b10 = (const float*)d_in[12];
    const float* g11 = (const float*)d_in[13]; const float* b11 = (const float*)d_in[14];
    const float* g12 = (const float*)d_in[15]; const float* b12 = (const float*)d_in[16];
    const float* w20 = (const float*)d_in[17];
    const float* w21 = (const float*)d_in[18];
    const float* w22 = (const float*)d_in[19];
    const float* g20 = (const float*)d_in[20]; const float* b20 = (const float*)d_in[21];
    const float* g21 = (const float*)d_in[22]; const float* b21 = (const float*)d_in[23];
    const float* g22 = (const float*)d_in[24]; const float* b22 = (const float*)d_in[25];
    float* out = (float*)d_out;

    void *flow0, *flow0us, *in1, *in2, *fps1, *fps2, *x0a, *ya, *yb, *yc;
    void *cf2, *cf1, *x0b, *za, *zb, *zc, *cf1o, *part, *ab;
    cudaGetSymbolAddress(&flow0, g_flow0);
    cudaGetSymbolAddress(&flow0us, g_flow0us);
    cudaGetSymbolAddress(&in1, g_in1);
    cudaGetSymbolAddress(&in2, g_in2);
    cudaGetSymbolAddress(&fps1, g_fps1);
    cudaGetSymbolAddress(&fps2, g_fps2);
    cudaGetSymbolAddress(&x0a, g_x0a);
    cudaGetSymbolAddress(&ya, g_ya);
    cudaGetSymbolAddress(&yb, g_yb);
    cudaGetSymbolAddress(&yc, g_yc);
    cudaGetSymbolAddress(&cf2, g_cf2);
    cudaGetSymbolAddress(&cf1, g_cf1);
    cudaGetSymbolAddress(&x0b, g_x0b);
    cudaGetSymbolAddress(&za, g_za);
    cudaGetSymbolAddress(&zb, g_zb);
    cudaGetSymbolAddress(&zc, g_zc);
    cudaGetSymbolAddress(&cf1o, g_cf1o);
    cudaGetSymbolAddress(&part, g_part);
    cudaGetSymbolAddress(&ab, g_ab);

    float* pmx1 = (float*)yc;
    float* pmn1 = (float*)yc + 8*512*64;
    float* pmx2 = (float*)zc;
    float* pmn2 = (float*)zc + (size_t)8*1024*128;

    // ONE side stream (R5-verified topology — passes the teardown memory check)
    cudaStream_t s2;
    cudaStreamCreateWithFlags(&s2, cudaStreamNonBlocking);
    cudaEvent_t eF, e1, e2;
    cudaEventCreateWithFlags(&eF, cudaEventDisableTiming);
    cudaEventCreateWithFlags(&e1, cudaEventDisableTiming);
    cudaEventCreateWithFlags(&e2, cudaEventDisableTiming);

    cudaEventRecord(eF, 0);
    cudaStreamWaitEvent(s2, eF, 0);
    k_fpsA<<<8, 256, 0, s2>>>(pc2, (int*)fps1);                                   // [0]
    cudaEventRecord(e1, s2);
    k_fpsB<<<8, 256, 0, s2>>>(pc1, (int*)fps2);                                   // [1]
    cudaEventRecord(e2, s2);
    k_inorm<<<dim3(8,2), 256>>>(f1, f2, (float*)in1, (float*)in2);                // [2]
    k_corr<<<dim3(8,8), 256>>>(f1, f2, (float*)in1, (float*)in2, pc3, q3, eps, (float*)flow0); // [3] probe
    k_prop<256,3,false><<<dim3(4,8), 128>>>(pc2, pc3, (float*)flow0, (float*)flow0us, 512);

    cudaStreamWaitEvent(0, e1, 0);
    k_g1<<<dim3(4,8), 128>>>(pc2, (float*)flow0us, (int*)fps1, (float*)x0a);

    k_conv<6,8,32,0,0><<<dim3(32,8), 128>>>((float*)x0a, w10, (float*)ab, (float*)ya, (float*)part, nullptr, nullptr, 8192, 32);
    k_fin<32><<<dim3(8,4), 256>>>((float*)part, g10, b10, (float*)ab, 32, 1.0f/8192.0f);
    k_conv<32,32,32,1,0><<<dim3(32,8), 128>>>((float*)ya, w11, (float*)ab, (float*)yb, (float*)part, nullptr, nullptr, 8192, 32);
    k_fin<32><<<dim3(8,4), 256>>>((float*)part, g11, b11, (float*)ab, 32, 1.0f/8192.0f);
    k_conv<32,32,64,1,1><<<dim3(64,8), 128>>>((float*)yb, w12, (float*)ab, nullptr, (float*)part, pmx1, pmn1, 8192, 64);
    k_fin<64><<<dim3(8,8), 256>>>((float*)part, g12, b12, (float*)ab, 64, 1.0f/8192.0f);
    k_pfin<64><<<dim3(512,8), 64>>>(pmx1, pmn1, (float*)ab, (float*)cf2);

    k_prop<512,64,false><<<dim3(8,8), 128>>>(pc1, pc2, (float*)cf2, (float*)cf1, 1024);
    cudaStreamWaitEvent(0, e2, 0);
    k_g2<<<dim3(8,8), 128>>>(pc1, (float*)cf1, (int*)fps2, (float*)x0b);

    k_conv<67,68,64,0,0><<<dim3(256,8), 128>>>((float*)x0b, w20, (float*)ab, (float*)za, (float*)part, nullptr, nullptr, 16384, 256);
    k_fin<64><<<dim3(8,8), 256>>>((float*)part, g20, b20, (float*)ab, 256, 1.0f/16384.0f);
    k_conv<64,64,64,1,0><<<dim3(256,8), 128>>>((float*)za, w21, (float*)ab, (float*)zb, (float*)part, nullptr, nullptr, 16384, 256);
    k_fin<64><<<dim3(8,8), 256>>>((float*)part, g21, b21, (float*)ab, 256, 1.0f/16384.0f);
    k_conv<64,64,128,1,1><<<dim3(512,8), 128>>>((float*)zb, w22, (float*)ab, nullptr, (float*)part, pmx2, pmn2, 16384, 512);
    k_fin<128><<<dim3(8,16), 256>>>((float*)part, g22, b22, (float*)ab, 512, 1.0f/16384.0f);
    k_pfin<128><<<dim3(1024,8), 128>>>(pmx2, pmn2, (float*)ab, (float*)cf1o);

    k_prop<1024,128,true><<<dim3(64,8), 128>>>(pc0, pc1, (float*)cf1o, out, 8192);
}